// round 5
// baseline (speedup 1.0000x reference)
#include <cuda_runtime.h>
#include <cuda_bf16.h>
#include <math.h>
#include <stdint.h>

#define BATCH 16
#define SEQ   1024
#define DIM   768
#define NHEAD 12
#define HDIM  64

#define M_TOK (BATCH * SEQ)      // 16384
#define QKV_E (3 * DIM)          // 2304

// -------------------- persistent scratch (bf16 hi/lo pairs) ----------------
__device__ __nv_bfloat16 g_xhi[(size_t)M_TOK * DIM];
__device__ __nv_bfloat16 g_xlo[(size_t)M_TOK * DIM];
__device__ __nv_bfloat16 g_wqkvhi[(size_t)QKV_E * DIM];
__device__ __nv_bfloat16 g_wqkvlo[(size_t)QKV_E * DIM];
__device__ __nv_bfloat16 g_wprojhi[(size_t)DIM * DIM];
__device__ __nv_bfloat16 g_wprojlo[(size_t)DIM * DIM];
__device__ __nv_bfloat16 g_qkvhi[(size_t)M_TOK * QKV_E];
__device__ __nv_bfloat16 g_qkvlo[(size_t)M_TOK * QKV_E];
__device__ __nv_bfloat16 g_aohi[(size_t)M_TOK * DIM];
__device__ __nv_bfloat16 g_aolo[(size_t)M_TOK * DIM];

// ----------------------------- helpers -------------------------------------
__device__ __forceinline__ uint32_t smem_u32(const void* p) {
    uint32_t a;
    asm("{ .reg .u64 t; cvta.to.shared.u64 t, %1; cvt.u32.u64 %0, t; }"
        : "=r"(a) : "l"(p));
    return a;
}

__device__ __forceinline__ void ldm_x4(uint32_t& r0, uint32_t& r1,
                                       uint32_t& r2, uint32_t& r3,
                                       uint32_t addr) {
    asm volatile("ldmatrix.sync.aligned.m8n8.x4.shared.b16 {%0,%1,%2,%3}, [%4];"
                 : "=r"(r0), "=r"(r1), "=r"(r2), "=r"(r3) : "r"(addr));
}

__device__ __forceinline__ void ldm_x4t(uint32_t& r0, uint32_t& r1,
                                        uint32_t& r2, uint32_t& r3,
                                        uint32_t addr) {
    asm volatile(
        "ldmatrix.sync.aligned.m8n8.x4.trans.shared.b16 {%0,%1,%2,%3}, [%4];"
        : "=r"(r0), "=r"(r1), "=r"(r2), "=r"(r3) : "r"(addr));
}

__device__ __forceinline__ void mma_bf16(float* c, const uint32_t* a,
                                         const uint32_t* b) {
    asm volatile(
        "mma.sync.aligned.m16n8k16.row.col.f32.bf16.bf16.f32 "
        "{%0,%1,%2,%3}, {%4,%5,%6,%7}, {%8,%9}, {%0,%1,%2,%3};"
        : "+f"(c[0]), "+f"(c[1]), "+f"(c[2]), "+f"(c[3])
        : "r"(a[0]), "r"(a[1]), "r"(a[2]), "r"(a[3]), "r"(b[0]), "r"(b[1]));
}

__device__ __forceinline__ void split2(float x, float y,
                                       uint32_t& hi, uint32_t& lo) {
    __nv_bfloat162 h = __floats2bfloat162_rn(x, y);
    __nv_bfloat162 l = __floats2bfloat162_rn(
        x - __bfloat162float(__low2bfloat16(h)),
        y - __bfloat162float(__high2bfloat16(h)));
    hi = *(uint32_t*)&h;
    lo = *(uint32_t*)&l;
}

__device__ __forceinline__ void cp16(uint32_t s, const void* g) {
    asm volatile("cp.async.cg.shared.global [%0], [%1], 16;" :: "r"(s), "l"(g));
}
__device__ __forceinline__ void cp_commit() {
    asm volatile("cp.async.commit_group;" ::: "memory");
}
__device__ __forceinline__ void cp_wait0() {
    asm volatile("cp.async.wait_group 0;" ::: "memory");
}

#define KROW 144   // 128 B data + 16 B pad per 64-bf16 row

// copy a 128-row x 128B tile (4 chunks/thread @256 thr)
__device__ __forceinline__ void cpa128(uint32_t sdst, const __nv_bfloat16* g,
                                       int stride, int tid) {
#pragma unroll
    for (int p = 0; p < 4; p++) {
        int c = tid + p * 256;
        int row = c >> 3, col = c & 7;
        cp16(sdst + row * KROW + col * 16, g + (size_t)row * stride + col * 8);
    }
}
// copy a 64-row x 128B tile (2 chunks/thread @256 thr)
__device__ __forceinline__ void cpa64(uint32_t sdst, const __nv_bfloat16* g,
                                      int stride, int tid) {
#pragma unroll
    for (int p = 0; p < 2; p++) {
        int c = tid + p * 256;
        int row = c >> 3, col = c & 7;
        cp16(sdst + row * KROW + col * 16, g + (size_t)row * stride + col * 8);
    }
}

// ---------------------- fp32 -> bf16 hi/lo split kernel --------------------
__global__ void split_kernel(const float4* __restrict__ src,
                             uint2* __restrict__ hi, uint2* __restrict__ lo,
                             int n4)
{
    int i = blockIdx.x * blockDim.x + threadIdx.x;
    if (i < n4) {
        float4 v = src[i];
        uint32_t h0, h1, l0, l1;
        split2(v.x, v.y, h0, l0);
        split2(v.z, v.w, h1, l1);
        hi[i] = make_uint2(h0, h1);
        lo[i] = make_uint2(l0, l1);
    }
}

// ===========================================================================
// Pre-split HMMA GEMM (NT): C = A * B^T. A,B given as bf16 hi/lo [rows,K].
// CTA 128x128, BK=64, 8 warps, cp.async double-buffered.
// Output: either fp32 C (+bias) or split bf16 Chi/Clo.
// ===========================================================================
#define GTILE  (128 * KROW)     // 18432
#define GSTAGE (4 * GTILE)      // 73728
#define GSMEM  (2 * GSTAGE)     // 147456

__global__ __launch_bounds__(256, 1) void gemm_ps_kernel(
    const __nv_bfloat16* __restrict__ Ahi, const __nv_bfloat16* __restrict__ Alo,
    const __nv_bfloat16* __restrict__ Bhi, const __nv_bfloat16* __restrict__ Blo,
    const float* __restrict__ bias, float* __restrict__ Cf,
    __nv_bfloat16* __restrict__ Chi, __nv_bfloat16* __restrict__ Clo,
    int Nn, int K)
{
    extern __shared__ __align__(128) char smc[];
    const uint32_t sb = smem_u32(smc);

    const int tid = threadIdx.x;
    const int lane = tid & 31;
    const int wid = tid >> 5;
    const int wm = wid >> 2;
    const int wn = wid & 3;
    const int bx = blockIdx.x;
    const int by = blockIdx.y;

    const __nv_bfloat16* Ah = Ahi + (size_t)by * 128 * K;
    const __nv_bfloat16* Al = Alo + (size_t)by * 128 * K;
    const __nv_bfloat16* Bh = Bhi + (size_t)bx * 128 * K;
    const __nv_bfloat16* Bl = Blo + (size_t)bx * 128 * K;

    const uint32_t a_lm = (uint32_t)((lane & 15) * KROW + (lane >> 4) * 16
                        + wm * 64 * KROW);
    const uint32_t b_lm = (uint32_t)((((lane >> 4) << 3) + (lane & 7)) * KROW
                        + ((lane >> 3) & 1) * 16 + wn * 32 * KROW);

    float c[4][4][4];
#pragma unroll
    for (int i = 0; i < 4; i++)
#pragma unroll
        for (int j = 0; j < 4; j++)
#pragma unroll
            for (int q = 0; q < 4; q++) c[i][j][q] = 0.0f;

    const int NC = K / 64;

    // prologue: stage 0
    {
        const uint32_t su = sb;
        cpa128(su,             Ah, K, tid);
        cpa128(su + GTILE,     Al, K, tid);
        cpa128(su + 2 * GTILE, Bh, K, tid);
        cpa128(su + 3 * GTILE, Bl, K, tid);
        cp_commit();
    }

    for (int ic = 0; ic < NC; ic++) {
        cp_wait0();
        __syncthreads();

        if (ic + 1 < NC) {
            const int k0 = (ic + 1) * 64;
            const uint32_t su = sb + (uint32_t)(((ic + 1) & 1) * GSTAGE);
            cpa128(su,             Ah + k0, K, tid);
            cpa128(su + GTILE,     Al + k0, K, tid);
            cpa128(su + 2 * GTILE, Bh + k0, K, tid);
            cpa128(su + 3 * GTILE, Bl + k0, K, tid);
            cp_commit();
        }

        const uint32_t su = sb + (uint32_t)((ic & 1) * GSTAGE);
#pragma unroll
        for (int ks = 0; ks < 4; ks++) {
            const uint32_t kofs = (uint32_t)(ks * 32);
            uint32_t ah[4][4], al[4][4], bh[4][2], bl[4][2];
#pragma unroll
            for (int im = 0; im < 4; im++) {
                uint32_t base = su + a_lm + (uint32_t)(im * 16 * KROW) + kofs;
                ldm_x4(ah[im][0], ah[im][1], ah[im][2], ah[im][3], base);
                ldm_x4(al[im][0], al[im][1], al[im][2], al[im][3], base + GTILE);
            }
#pragma unroll
            for (int in2 = 0; in2 < 2; in2++) {
                uint32_t base = su + 2 * GTILE + b_lm
                              + (uint32_t)(in2 * 16 * KROW) + kofs;
                uint32_t r0, r1, r2, r3;
                ldm_x4(r0, r1, r2, r3, base);
                bh[in2 * 2][0] = r0; bh[in2 * 2][1] = r1;
                bh[in2 * 2 + 1][0] = r2; bh[in2 * 2 + 1][1] = r3;
                ldm_x4(r0, r1, r2, r3, base + GTILE);
                bl[in2 * 2][0] = r0; bl[in2 * 2][1] = r1;
                bl[in2 * 2 + 1][0] = r2; bl[in2 * 2 + 1][1] = r3;
            }
#pragma unroll
            for (int im = 0; im < 4; im++)
#pragma unroll
                for (int inn = 0; inn < 4; inn++) {
                    mma_bf16(c[im][inn], ah[im], bh[inn]);
                    mma_bf16(c[im][inn], ah[im], bl[inn]);
                    mma_bf16(c[im][inn], al[im], bh[inn]);
                }
        }
    }

    // epilogue
#pragma unroll
    for (int im = 0; im < 4; im++) {
        const size_t row = (size_t)by * 128 + wm * 64 + im * 16 + (lane >> 2);
#pragma unroll
        for (int inn = 0; inn < 4; inn++) {
            const int col = bx * 128 + wn * 32 + inn * 8 + (lane & 3) * 2;
            if (Cf) {
                float b0 = 0.0f, b1 = 0.0f;
                if (bias) { b0 = bias[col]; b1 = bias[col + 1]; }
                *(float2*)(Cf + row * Nn + col) =
                    make_float2(c[im][inn][0] + b0, c[im][inn][1] + b1);
                *(float2*)(Cf + (row + 8) * Nn + col) =
                    make_float2(c[im][inn][2] + b0, c[im][inn][3] + b1);
            } else {
                uint32_t h, l;
                split2(c[im][inn][0], c[im][inn][1], h, l);
                *(uint32_t*)&Chi[row * Nn + col] = h;
                *(uint32_t*)&Clo[row * Nn + col] = l;
                split2(c[im][inn][2], c[im][inn][3], h, l);
                *(uint32_t*)&Chi[(row + 8) * Nn + col] = h;
                *(uint32_t*)&Clo[(row + 8) * Nn + col] = l;
            }
        }
    }
}

// ===========================================================================
// Flash attention, pre-split bf16 inputs, cp.async double-buffered K/V,
// V via ldmatrix.trans, Q fragments hoisted to registers.
// CTA = 128 queries x one (b,h); 8 warps x 16 query rows; key tile 64.
// ===========================================================================
#define AQHI  0
#define AQLO  GTILE                 // 18432
#define AKV   (2 * GTILE)           // 36864
#define KTILE (64 * KROW)           // 9216
#define KVSTG (4 * KTILE)           // 36864
#define ASMEM (AKV + 2 * KVSTG)     // 110592

__global__ __launch_bounds__(256, 1) void attn_ps_kernel(
    const __nv_bfloat16* __restrict__ qkvhi,
    const __nv_bfloat16* __restrict__ qkvlo,
    __nv_bfloat16* __restrict__ aohi,
    __nv_bfloat16* __restrict__ aolo)
{
    extern __shared__ __align__(128) char smc[];
    const uint32_t sb = smem_u32(smc);

    const int tid = threadIdx.x;
    const int lane = tid & 31;
    const int wid = tid >> 5;

    const int qt = blockIdx.x;        // 0..7
    const int bh = blockIdx.y;        // 0..191
    const int b = bh / NHEAD;
    const int h = bh % NHEAD;

    const int rs = QKV_E;             // 2304
    const size_t qoff = ((size_t)(b * SEQ + qt * 128)) * rs + h * HDIM;
    const size_t koff = ((size_t)(b * SEQ)) * rs + (NHEAD + h) * HDIM;
    const size_t voff = ((size_t)(b * SEQ)) * rs + (2 * NHEAD + h) * HDIM;

    // prologue: Q (both) + KV tile 0
    cpa128(sb + AQHI, qkvhi + qoff, rs, tid);
    cpa128(sb + AQLO, qkvlo + qoff, rs, tid);
    cpa64(sb + AKV,             qkvhi + koff, rs, tid);
    cpa64(sb + AKV + KTILE,     qkvlo + koff, rs, tid);
    cpa64(sb + AKV + 2 * KTILE, qkvhi + voff, rs, tid);
    cpa64(sb + AKV + 3 * KTILE, qkvlo + voff, rs, tid);
    cp_commit();

    const uint32_t a_lm = (uint32_t)((lane & 15) * KROW + (lane >> 4) * 16);
    const uint32_t b_lm = (uint32_t)((((lane >> 4) << 3) + (lane & 7)) * KROW
                        + ((lane >> 3) & 1) * 16);

    uint32_t qh[4][4], ql[4][4];      // hoisted Q fragments

    float m0 = -INFINITY, m1 = -INFINITY, l0a = 0.0f, l1a = 0.0f;
    float o[8][4];
#pragma unroll
    for (int nb = 0; nb < 8; nb++)
#pragma unroll
        for (int q = 0; q < 4; q++) o[nb][q] = 0.0f;

    for (int jt = 0; jt < SEQ / 64; jt++) {
        cp_wait0();
        __syncthreads();

        if (jt + 1 < SEQ / 64) {
            const uint32_t su = sb + AKV + (uint32_t)(((jt + 1) & 1) * KVSTG);
            const size_t ro = (size_t)((jt + 1) * 64) * rs;
            cpa64(su,             qkvhi + koff + ro, rs, tid);
            cpa64(su + KTILE,     qkvlo + koff + ro, rs, tid);
            cpa64(su + 2 * KTILE, qkvhi + voff + ro, rs, tid);
            cpa64(su + 3 * KTILE, qkvlo + voff + ro, rs, tid);
            cp_commit();
        }

        if (jt == 0) {
            const uint32_t qbase = sb + AQHI + (uint32_t)(wid * 16 * KROW) + a_lm;
#pragma unroll
            for (int ks = 0; ks < 4; ks++) {
                ldm_x4(qh[ks][0], qh[ks][1], qh[ks][2], qh[ks][3],
                       qbase + ks * 32);
                ldm_x4(ql[ks][0], ql[ks][1], ql[ks][2], ql[ks][3],
                       qbase + (AQLO - AQHI) + ks * 32);
            }
        }

        const uint32_t st = sb + AKV + (uint32_t)((jt & 1) * KVSTG);

        // ---- S = Q K^T, 3-term split ----
        float s[8][4];
#pragma unroll
        for (int nb = 0; nb < 8; nb++)
#pragma unroll
            for (int q = 0; q < 4; q++) s[nb][q] = 0.0f;

#pragma unroll
        for (int ks = 0; ks < 4; ks++) {
#pragma unroll
            for (int nb2 = 0; nb2 < 4; nb2++) {
                const uint32_t kb = st + (uint32_t)(nb2 * 16 * KROW)
                                  + b_lm + ks * 32;
                uint32_t r0, r1, r2, r3, t0, t1, t2, t3;
                ldm_x4(r0, r1, r2, r3, kb);
                ldm_x4(t0, t1, t2, t3, kb + KTILE);
                uint32_t bh0[2] = {r0, r1}, bh1[2] = {r2, r3};
                uint32_t bl0[2] = {t0, t1}, bl1[2] = {t2, t3};
                mma_bf16(s[2 * nb2],     qh[ks], bh0);
                mma_bf16(s[2 * nb2],     qh[ks], bl0);
                mma_bf16(s[2 * nb2],     ql[ks], bh0);
                mma_bf16(s[2 * nb2 + 1], qh[ks], bh1);
                mma_bf16(s[2 * nb2 + 1], qh[ks], bl1);
                mma_bf16(s[2 * nb2 + 1], ql[ks], bh1);
            }
        }

        // ---- online softmax (scale 0.125 applied here) ----
        float mx0 = -INFINITY, mx1 = -INFINITY;
#pragma unroll
        for (int nb = 0; nb < 8; nb++) {
            s[nb][0] *= 0.125f; s[nb][1] *= 0.125f;
            s[nb][2] *= 0.125f; s[nb][3] *= 0.125f;
            mx0 = fmaxf(mx0, fmaxf(s[nb][0], s[nb][1]));
            mx1 = fmaxf(mx1, fmaxf(s[nb][2], s[nb][3]));
        }
        mx0 = fmaxf(mx0, __shfl_xor_sync(0xffffffffu, mx0, 1));
        mx0 = fmaxf(mx0, __shfl_xor_sync(0xffffffffu, mx0, 2));
        mx1 = fmaxf(mx1, __shfl_xor_sync(0xffffffffu, mx1, 1));
        mx1 = fmaxf(mx1, __shfl_xor_sync(0xffffffffu, mx1, 2));

        const float mn0 = fmaxf(m0, mx0);
        const float mn1 = fmaxf(m1, mx1);
        const float al0 = __expf(m0 - mn0);
        const float al1 = __expf(m1 - mn1);
        m0 = mn0; m1 = mn1;

        float rs0 = 0.0f, rs1 = 0.0f;
#pragma unroll
        for (int nb = 0; nb < 8; nb++) {
            s[nb][0] = __expf(s[nb][0] - m0);
            s[nb][1] = __expf(s[nb][1] - m0);
            s[nb][2] = __expf(s[nb][2] - m1);
            s[nb][3] = __expf(s[nb][3] - m1);
            rs0 += s[nb][0] + s[nb][1];
            rs1 += s[nb][2] + s[nb][3];
        }
        rs0 += __shfl_xor_sync(0xffffffffu, rs0, 1);
        rs0 += __shfl_xor_sync(0xffffffffu, rs0, 2);
        rs1 += __shfl_xor_sync(0xffffffffu, rs1, 1);
        rs1 += __shfl_xor_sync(0xffffffffu, rs1, 2);
        l0a = l0a * al0 + rs0;
        l1a = l1a * al1 + rs1;

#pragma unroll
        for (int nb = 0; nb < 8; nb++) {
            o[nb][0] *= al0; o[nb][1] *= al0;
            o[nb][2] *= al1; o[nb][3] *= al1;
        }

        // ---- O += P V (P split in regs; V via ldmatrix.trans) ----
#pragma unroll
        for (int ks2 = 0; ks2 < 4; ks2++) {
            uint32_t ph[4], pl[4];
            split2(s[2 * ks2][0],     s[2 * ks2][1],     ph[0], pl[0]);
            split2(s[2 * ks2][2],     s[2 * ks2][3],     ph[1], pl[1]);
            split2(s[2 * ks2 + 1][0], s[2 * ks2 + 1][1], ph[2], pl[2]);
            split2(s[2 * ks2 + 1][2], s[2 * ks2 + 1][3], ph[3], pl[3]);
#pragma unroll
            for (int nb2 = 0; nb2 < 4; nb2++) {
                const uint32_t vb = st + 2 * KTILE
                                  + (uint32_t)(ks2 * 16 * KROW)
                                  + (uint32_t)(nb2 * 32) + a_lm;
                uint32_t r0, r1, r2, r3, t0, t1, t2, t3;
                ldm_x4t(r0, r1, r2, r3, vb);
                ldm_x4t(t0, t1, t2, t3, vb + KTILE);
                uint32_t vh0[2] = {r0, r1}, vh1[2] = {r2, r3};
                uint32_t vl0[2] = {t0, t1}, vl1[2] = {t2, t3};
                mma_bf16(o[2 * nb2],     ph, vh0);
                mma_bf16(o[2 * nb2],     ph, vl0);
                mma_bf16(o[2 * nb2],     pl, vh0);
                mma_bf16(o[2 * nb2 + 1], ph, vh1);
                mma_bf16(o[2 * nb2 + 1], ph, vl1);
                mma_bf16(o[2 * nb2 + 1], pl, vh1);
            }
        }
    }

    // ---- epilogue: normalize, split, store ao hi/lo ----
    const float inv0 = 1.0f / l0a;
    const float inv1 = 1.0f / l1a;
    const size_t tok0 = (size_t)b * SEQ + qt * 128 + wid * 16 + (lane >> 2);
#pragma unroll
    for (int nb = 0; nb < 8; nb++) {
        const int col = h * HDIM + nb * 8 + (lane & 3) * 2;
        uint32_t hh, ll;
        split2(o[nb][0] * inv0, o[nb][1] * inv0, hh, ll);
        *(uint32_t*)&aohi[tok0 * DIM + col] = hh;
        *(uint32_t*)&aolo[tok0 * DIM + col] = ll;
        split2(o[nb][2] * inv1, o[nb][3] * inv1, hh, ll);
        *(uint32_t*)&aohi[(tok0 + 8) * DIM + col] = hh;
        *(uint32_t*)&aolo[(tok0 + 8) * DIM + col] = ll;
    }
}

// ===========================================================================
extern "C" void kernel_launch(void* const* d_in, const int* in_sizes, int n_in,
                              void* d_out, int out_size)
{
    const float* x      = (const float*)d_in[0];
    const float* w_qkv  = (const float*)d_in[1];
    const float* w_proj = (const float*)d_in[2];
    const float* b_proj = (const float*)d_in[3];
    float* out = (float*)d_out;

    __nv_bfloat16 *xhi, *xlo, *wqh, *wql, *wph, *wpl, *qh, *qlo, *ahi, *alo;
    cudaGetSymbolAddress((void**)&xhi, g_xhi);
    cudaGetSymbolAddress((void**)&xlo, g_xlo);
    cudaGetSymbolAddress((void**)&wqh, g_wqkvhi);
    cudaGetSymbolAddress((void**)&wql, g_wqkvlo);
    cudaGetSymbolAddress((void**)&wph, g_wprojhi);
    cudaGetSymbolAddress((void**)&wpl, g_wprojlo);
    cudaGetSymbolAddress((void**)&qh,  g_qkvhi);
    cudaGetSymbolAddress((void**)&qlo, g_qkvlo);
    cudaGetSymbolAddress((void**)&ahi, g_aohi);
    cudaGetSymbolAddress((void**)&alo, g_aolo);

    cudaFuncSetAttribute(gemm_ps_kernel,
                         cudaFuncAttributeMaxDynamicSharedMemorySize, GSMEM);
    cudaFuncSetAttribute(attn_ps_kernel,
                         cudaFuncAttributeMaxDynamicSharedMemorySize, ASMEM);

    // 0) split inputs into bf16 hi/lo
    {
        int n4 = M_TOK * DIM / 4;       // 3145728
        split_kernel<<<n4 / 256, 256>>>((const float4*)x,
                                        (uint2*)xhi, (uint2*)xlo, n4);
        n4 = QKV_E * DIM / 4;           // 442368
        split_kernel<<<n4 / 256, 256>>>((const float4*)w_qkv,
                                        (uint2*)wqh, (uint2*)wql, n4);
        n4 = DIM * DIM / 4;             // 147456
        split_kernel<<<n4 / 256, 256>>>((const float4*)w_proj,
                                        (uint2*)wph, (uint2*)wpl, n4);
    }

    // 1) QKV projection -> split qkv
    dim3 g1(QKV_E / 128, M_TOK / 128);   // (18, 128)
    gemm_ps_kernel<<<g1, 256, GSMEM>>>(xhi, xlo, wqh, wql,
                                       nullptr, nullptr, qh, qlo,
                                       QKV_E, DIM);

    // 2) Attention -> split ao
    dim3 g2(SEQ / 128, BATCH * NHEAD);   // (8, 192)
    attn_ps_kernel<<<g2, 256, ASMEM>>>(qh, qlo, ahi, alo);

    // 3) Output projection -> fp32 out + bias
    dim3 g3(DIM / 128, M_TOK / 128);     // (6, 128)
    gemm_ps_kernel<<<g3, 256, GSMEM>>>(ahi, alo, wph, wpl,
                                       b_proj, out, nullptr, nullptr,
                                       DIM, DIM);
}

// round 6
// speedup vs baseline: 1.1524x; 1.1524x over previous
#include <cuda_runtime.h>
#include <cuda_bf16.h>
#include <math.h>
#include <stdint.h>

#define BATCH 16
#define SEQ   1024
#define DIM   768
#define NHEAD 12
#define HDIM  64

#define M_TOK (BATCH * SEQ)      // 16384
#define QKV_E (3 * DIM)          // 2304

#define KROW 144                 // bytes per 64-bf16 row (128B data + 16B pad)
#define TB   (128 * KROW)        // 18432: 128-row tile
#define KTB  (64 * KROW)         // 9216:  64-row tile
#define NKS  (DIM / 64)          // 12 k-stages

// ----------------- blocked scratch (bf16 hi/lo, 144B-pitch tiles) ----------
// GEMM operand blocks: [row_tile][k_stage][TB]
__device__ __align__(128) char g_xhi[(size_t)128 * NKS * TB];
__device__ __align__(128) char g_xlo[(size_t)128 * NKS * TB];
__device__ __align__(128) char g_wqh[(size_t)18 * NKS * TB];
__device__ __align__(128) char g_wql[(size_t)18 * NKS * TB];
__device__ __align__(128) char g_wph[(size_t)6 * NKS * TB];
__device__ __align__(128) char g_wpl[(size_t)6 * NKS * TB];
// qkv blocked for attention: [b][kind(3)][h][st(16)][KTB]
__device__ __align__(128) char g_qh[(size_t)BATCH * 3 * NHEAD * 16 * KTB];
__device__ __align__(128) char g_ql[(size_t)BATCH * 3 * NHEAD * 16 * KTB];
// ao blocked for proj GEMM: [m_tile(128)][k_stage(12)][TB]
__device__ __align__(128) char g_ah[(size_t)128 * NKS * TB];
__device__ __align__(128) char g_al[(size_t)128 * NKS * TB];

// ----------------------------- helpers -------------------------------------
__device__ __forceinline__ uint32_t smem_u32(const void* p) {
    uint32_t a;
    asm("{ .reg .u64 t; cvta.to.shared.u64 t, %1; cvt.u32.u64 %0, t; }"
        : "=r"(a) : "l"(p));
    return a;
}

__device__ __forceinline__ void ldm_x4(uint32_t& r0, uint32_t& r1,
                                       uint32_t& r2, uint32_t& r3,
                                       uint32_t addr) {
    asm volatile("ldmatrix.sync.aligned.m8n8.x4.shared.b16 {%0,%1,%2,%3}, [%4];"
                 : "=r"(r0), "=r"(r1), "=r"(r2), "=r"(r3) : "r"(addr));
}

__device__ __forceinline__ void ldm_x4t(uint32_t& r0, uint32_t& r1,
                                        uint32_t& r2, uint32_t& r3,
                                        uint32_t addr) {
    asm volatile(
        "ldmatrix.sync.aligned.m8n8.x4.trans.shared.b16 {%0,%1,%2,%3}, [%4];"
        : "=r"(r0), "=r"(r1), "=r"(r2), "=r"(r3) : "r"(addr));
}

__device__ __forceinline__ void mma_bf16(float* c, const uint32_t* a,
                                         const uint32_t* b) {
    asm volatile(
        "mma.sync.aligned.m16n8k16.row.col.f32.bf16.bf16.f32 "
        "{%0,%1,%2,%3}, {%4,%5,%6,%7}, {%8,%9}, {%0,%1,%2,%3};"
        : "+f"(c[0]), "+f"(c[1]), "+f"(c[2]), "+f"(c[3])
        : "r"(a[0]), "r"(a[1]), "r"(a[2]), "r"(a[3]), "r"(b[0]), "r"(b[1]));
}

__device__ __forceinline__ void split2(float x, float y,
                                       uint32_t& hi, uint32_t& lo) {
    __nv_bfloat162 h = __floats2bfloat162_rn(x, y);
    __nv_bfloat162 l = __floats2bfloat162_rn(
        x - __bfloat162float(__low2bfloat16(h)),
        y - __bfloat162float(__high2bfloat16(h)));
    hi = *(uint32_t*)&h;
    lo = *(uint32_t*)&l;
}

__device__ __forceinline__ void mbar_init(uint32_t mb, uint32_t cnt) {
    asm volatile("mbarrier.init.shared.b64 [%0], %1;"
                 :: "r"(mb), "r"(cnt) : "memory");
}
__device__ __forceinline__ void mbar_expect(uint32_t mb, uint32_t bytes) {
    asm volatile("mbarrier.arrive.expect_tx.shared.b64 _, [%0], %1;"
                 :: "r"(mb), "r"(bytes) : "memory");
}
__device__ __forceinline__ void mbar_wait(uint32_t mb, uint32_t parity) {
    asm volatile(
        "{\n\t.reg .pred P;\n\t"
        "WL%=:\n\t"
        "mbarrier.try_wait.parity.acquire.cta.shared::cta.b64 P, [%0], %1, 0x989680;\n\t"
        "@P bra WD%=;\n\t"
        "bra WL%=;\n\t"
        "WD%=:\n\t}"
        :: "r"(mb), "r"(parity) : "memory");
}
__device__ __forceinline__ void bulkcp(uint32_t sdst, const void* gsrc,
                                       uint32_t bytes, uint32_t mb) {
    asm volatile(
        "cp.async.bulk.shared::cta.global.mbarrier::complete_tx::bytes "
        "[%0], [%1], %2, [%3];"
        :: "r"(sdst), "l"(gsrc), "r"(bytes), "r"(mb) : "memory");
}

// ------------- fp32 [M,768] -> blocked split bf16 hi/lo tiles ---------------
__global__ void split_blk_kernel(const float4* __restrict__ src,
                                 char* __restrict__ hi, char* __restrict__ lo,
                                 int n4)
{
    int i = blockIdx.x * blockDim.x + threadIdx.x;
    if (i >= n4) return;
    int idx = i * 4;
    int m = idx / DIM;
    int e = idx - m * DIM;
    float4 v = src[i];
    uint32_t h0, h1, l0, l1;
    split2(v.x, v.y, h0, l0);
    split2(v.z, v.w, h1, l1);
    size_t off = ((size_t)(m >> 7) * NKS + (e >> 6)) * TB
               + (size_t)(m & 127) * KROW + (e & 63) * 2;
    *(uint2*)(hi + off) = make_uint2(h0, h1);
    *(uint2*)(lo + off) = make_uint2(l0, l1);
}

// ===========================================================================
// Bulk-DMA split-bf16 HMMA GEMM (NT), K=768 fixed, CTA 128x128, BK=64.
// mode 0: write blocked qkv (hi/lo). mode 1: write fp32 C + bias.
// ===========================================================================
#define GSMEM (128 + 2 * 4 * TB)   // bars + 2 stages x {Ahi,Alo,Bhi,Blo}

__global__ __launch_bounds__(256, 1) void gemm_blk_kernel(
    const char* __restrict__ Ahi, const char* __restrict__ Alo,
    const char* __restrict__ Bhi, const char* __restrict__ Blo,
    const float* __restrict__ bias, float* __restrict__ Cf,
    char* __restrict__ Qhi, char* __restrict__ Qlo,
    int Nn, int mode)
{
    extern __shared__ __align__(128) char smc[];
    const uint32_t sb = smem_u32(smc);
    const uint32_t bufs = sb + 128;

    const int tid = threadIdx.x;
    const int lane = tid & 31;
    const int wid = tid >> 5;
    const int wm = wid >> 2;
    const int wn = wid & 3;
    const int bx = blockIdx.x;
    const int by = blockIdx.y;

    if (tid == 0) { mbar_init(sb, 1); mbar_init(sb + 8, 1); }
    __syncthreads();

    const char* Asrc[2] = {Ahi + (size_t)by * NKS * TB,
                           Alo + (size_t)by * NKS * TB};
    const char* Bsrc[2] = {Bhi + (size_t)bx * NKS * TB,
                           Blo + (size_t)bx * NKS * TB};

    if (tid == 0) {
        mbar_expect(sb, 4 * TB);
        bulkcp(bufs + 0 * TB, Asrc[0], TB, sb);
        bulkcp(bufs + 1 * TB, Asrc[1], TB, sb);
        bulkcp(bufs + 2 * TB, Bsrc[0], TB, sb);
        bulkcp(bufs + 3 * TB, Bsrc[1], TB, sb);
    }

    const uint32_t a_lm = (uint32_t)((lane & 15) * KROW + (lane >> 4) * 16
                        + wm * 64 * KROW);
    const uint32_t b_lm = (uint32_t)((((lane >> 4) << 3) + (lane & 7)) * KROW
                        + ((lane >> 3) & 1) * 16 + wn * 32 * KROW);

    float c[4][4][4];
#pragma unroll
    for (int i = 0; i < 4; i++)
#pragma unroll
        for (int j = 0; j < 4; j++)
#pragma unroll
            for (int q = 0; q < 4; q++) c[i][j][q] = 0.0f;

    uint32_t ph[2] = {0, 0};

    for (int ic = 0; ic < NKS; ic++) {
        if (tid == 0 && ic + 1 < NKS) {
            const uint32_t mb = sb + ((ic + 1) & 1) * 8;
            const uint32_t bu = bufs + ((ic + 1) & 1) * 4 * TB;
            const size_t go = (size_t)(ic + 1) * TB;
            mbar_expect(mb, 4 * TB);
            bulkcp(bu + 0 * TB, Asrc[0] + go, TB, mb);
            bulkcp(bu + 1 * TB, Asrc[1] + go, TB, mb);
            bulkcp(bu + 2 * TB, Bsrc[0] + go, TB, mb);
            bulkcp(bu + 3 * TB, Bsrc[1] + go, TB, mb);
        }
        const int bs = ic & 1;
        mbar_wait(sb + bs * 8, ph[bs]);
        ph[bs] ^= 1;

        const uint32_t su = bufs + (uint32_t)(bs * 4 * TB);
#pragma unroll
        for (int ks = 0; ks < 4; ks++) {
            const uint32_t kofs = (uint32_t)(ks * 32);
            uint32_t ah[4][4], al[4][4], bh[4][2], bl[4][2];
#pragma unroll
            for (int im = 0; im < 4; im++) {
                uint32_t base = su + a_lm + (uint32_t)(im * 16 * KROW) + kofs;
                ldm_x4(ah[im][0], ah[im][1], ah[im][2], ah[im][3], base);
                ldm_x4(al[im][0], al[im][1], al[im][2], al[im][3], base + TB);
            }
#pragma unroll
            for (int in2 = 0; in2 < 2; in2++) {
                uint32_t base = su + 2 * TB + b_lm
                              + (uint32_t)(in2 * 16 * KROW) + kofs;
                uint32_t r0, r1, r2, r3;
                ldm_x4(r0, r1, r2, r3, base);
                bh[in2 * 2][0] = r0; bh[in2 * 2][1] = r1;
                bh[in2 * 2 + 1][0] = r2; bh[in2 * 2 + 1][1] = r3;
                ldm_x4(r0, r1, r2, r3, base + TB);
                bl[in2 * 2][0] = r0; bl[in2 * 2][1] = r1;
                bl[in2 * 2 + 1][0] = r2; bl[in2 * 2 + 1][1] = r3;
            }
#pragma unroll
            for (int im = 0; im < 4; im++)
#pragma unroll
                for (int inn = 0; inn < 4; inn++) {
                    mma_bf16(c[im][inn], ah[im], bh[inn]);
                    mma_bf16(c[im][inn], ah[im], bl[inn]);
                    mma_bf16(c[im][inn], al[im], bh[inn]);
                }
        }
        __syncthreads();
    }

    if (mode == 1) {
        // fp32 output + bias (row-major [M, Nn])
#pragma unroll
        for (int im = 0; im < 4; im++) {
            const size_t row = (size_t)by * 128 + wm * 64 + im * 16 + (lane >> 2);
#pragma unroll
            for (int inn = 0; inn < 4; inn++) {
                const int col = bx * 128 + wn * 32 + inn * 8 + (lane & 3) * 2;
                float b0 = bias[col], b1 = bias[col + 1];
                *(float2*)(Cf + row * Nn + col) =
                    make_float2(c[im][inn][0] + b0, c[im][inn][1] + b1);
                *(float2*)(Cf + (row + 8) * Nn + col) =
                    make_float2(c[im][inn][2] + b0, c[im][inn][3] + b1);
            }
        }
    } else {
        // blocked qkv write: [b][kind][h][st][64 x KROW]
        const int bq = by >> 3;
#pragma unroll
        for (int inn = 0; inn < 4; inn++) {
            const int e = bx * 128 + wn * 32 + inn * 8 + (lane & 3) * 2;
            const int g = e >> 6;
            const int kind = g / 12;
            const int hh = g - kind * 12;
            const int cc = (e & 63) * 2;
            const size_t gb = ((size_t)((bq * 3 + kind) * 12 + hh)) * (16 * KTB);
#pragma unroll
            for (int im = 0; im < 4; im++) {
                const int seq0 = (by & 7) * 128 + wm * 64 + im * 16 + (lane >> 2);
                const size_t off = gb + (size_t)(seq0 >> 6) * KTB
                                 + (size_t)(seq0 & 63) * KROW + cc;
                uint32_t h, l;
                split2(c[im][inn][0], c[im][inn][1], h, l);
                *(uint32_t*)(Qhi + off) = h;
                *(uint32_t*)(Qlo + off) = l;
                const int seq1 = seq0 + 8;
                const size_t off1 = gb + (size_t)(seq1 >> 6) * KTB
                                  + (size_t)(seq1 & 63) * KROW + cc;
                split2(c[im][inn][2], c[im][inn][3], h, l);
                *(uint32_t*)(Qhi + off1) = h;
                *(uint32_t*)(Qlo + off1) = l;
            }
        }
    }
}

// ===========================================================================
// Flash attention, bulk-DMA loads from blocked qkv, split-bf16 HMMA.
// CTA = 128 queries x one (b,h); 8 warps x 16 rows; key tile 64.
// smem: [bars 128][Qhi TB][Qlo TB][stage0: Kh,Kl,Vh,Vl x KTB][stage1: ...]
// ===========================================================================
#define AQOFF 128
#define AKV0  (AQOFF + 2 * TB)
#define ASTG  (4 * KTB)                 // 36864
#define ASMEM (AKV0 + 2 * ASTG)

__global__ __launch_bounds__(256, 1) void attn_blk_kernel(
    const char* __restrict__ qh, const char* __restrict__ ql,
    char* __restrict__ ah, char* __restrict__ al)
{
    extern __shared__ __align__(128) char smc[];
    const uint32_t sb = smem_u32(smc);

    const int tid = threadIdx.x;
    const int lane = tid & 31;
    const int wid = tid >> 5;

    const int qt = blockIdx.x;        // 0..7
    const int bh = blockIdx.y;        // 0..191
    const int b = bh / NHEAD;
    const int h = bh % NHEAD;

    const size_t baseQ = ((size_t)((b * 3 + 0) * 12 + h)) * (16 * KTB);
    const size_t baseK = ((size_t)((b * 3 + 1) * 12 + h)) * (16 * KTB);
    const size_t baseV = ((size_t)((b * 3 + 2) * 12 + h)) * (16 * KTB);

    // bars: sb+0 = Q, sb+8 = kv0, sb+16 = kv1
    if (tid == 0) {
        mbar_init(sb, 1); mbar_init(sb + 8, 1); mbar_init(sb + 16, 1);
    }
    __syncthreads();

    if (tid == 0) {
        mbar_expect(sb, 2 * TB);
        bulkcp(sb + AQOFF,      qh + baseQ + (size_t)qt * TB, TB, sb);
        bulkcp(sb + AQOFF + TB, ql + baseQ + (size_t)qt * TB, TB, sb);
        mbar_expect(sb + 8, ASTG);
        bulkcp(sb + AKV0 + 0 * KTB, qh + baseK, KTB, sb + 8);
        bulkcp(sb + AKV0 + 1 * KTB, ql + baseK, KTB, sb + 8);
        bulkcp(sb + AKV0 + 2 * KTB, qh + baseV, KTB, sb + 8);
        bulkcp(sb + AKV0 + 3 * KTB, ql + baseV, KTB, sb + 8);
    }

    const uint32_t a_lm = (uint32_t)((lane & 15) * KROW + (lane >> 4) * 16);
    const uint32_t b_lm = (uint32_t)((((lane >> 4) << 3) + (lane & 7)) * KROW
                        + ((lane >> 3) & 1) * 16);

    uint32_t qfh[4][4], qfl[4][4];

    float m0 = -INFINITY, m1 = -INFINITY, l0a = 0.0f, l1a = 0.0f;
    float o[8][4];
#pragma unroll
    for (int nb = 0; nb < 8; nb++)
#pragma unroll
        for (int q = 0; q < 4; q++) o[nb][q] = 0.0f;

    uint32_t ph[2] = {0, 0};

    for (int jt = 0; jt < SEQ / 64; jt++) {
        if (tid == 0 && jt + 1 < SEQ / 64) {
            const uint32_t mb = sb + 8 + ((jt + 1) & 1) * 8;
            const uint32_t bu = sb + AKV0 + ((jt + 1) & 1) * ASTG;
            const size_t go = (size_t)(jt + 1) * KTB;
            mbar_expect(mb, ASTG);
            bulkcp(bu + 0 * KTB, qh + baseK + go, KTB, mb);
            bulkcp(bu + 1 * KTB, ql + baseK + go, KTB, mb);
            bulkcp(bu + 2 * KTB, qh + baseV + go, KTB, mb);
            bulkcp(bu + 3 * KTB, ql + baseV + go, KTB, mb);
        }
        const int bs = jt & 1;
        mbar_wait(sb + 8 + bs * 8, ph[bs]);
        ph[bs] ^= 1;

        if (jt == 0) {
            mbar_wait(sb, 0);
            const uint32_t qbase = sb + AQOFF + (uint32_t)(wid * 16 * KROW) + a_lm;
#pragma unroll
            for (int ks = 0; ks < 4; ks++) {
                ldm_x4(qfh[ks][0], qfh[ks][1], qfh[ks][2], qfh[ks][3],
                       qbase + ks * 32);
                ldm_x4(qfl[ks][0], qfl[ks][1], qfl[ks][2], qfl[ks][3],
                       qbase + TB + ks * 32);
            }
        }

        const uint32_t st = sb + AKV0 + (uint32_t)(bs * ASTG);

        // ---- S = Q K^T, 3-term split ----
        float s[8][4];
#pragma unroll
        for (int nb = 0; nb < 8; nb++)
#pragma unroll
            for (int q = 0; q < 4; q++) s[nb][q] = 0.0f;

#pragma unroll
        for (int ks = 0; ks < 4; ks++) {
#pragma unroll
            for (int nb2 = 0; nb2 < 4; nb2++) {
                const uint32_t kb = st + (uint32_t)(nb2 * 16 * KROW)
                                  + b_lm + ks * 32;
                uint32_t r0, r1, r2, r3, t0, t1, t2, t3;
                ldm_x4(r0, r1, r2, r3, kb);
                ldm_x4(t0, t1, t2, t3, kb + KTB);
                uint32_t bh0[2] = {r0, r1}, bh1[2] = {r2, r3};
                uint32_t bl0[2] = {t0, t1}, bl1[2] = {t2, t3};
                mma_bf16(s[2 * nb2],     qfh[ks], bh0);
                mma_bf16(s[2 * nb2],     qfh[ks], bl0);
                mma_bf16(s[2 * nb2],     qfl[ks], bh0);
                mma_bf16(s[2 * nb2 + 1], qfh[ks], bh1);
                mma_bf16(s[2 * nb2 + 1], qfh[ks], bl1);
                mma_bf16(s[2 * nb2 + 1], qfl[ks], bh1);
            }
        }

        // ---- online softmax ----
        float mx0 = -INFINITY, mx1 = -INFINITY;
#pragma unroll
        for (int nb = 0; nb < 8; nb++) {
            s[nb][0] *= 0.125f; s[nb][1] *= 0.125f;
            s[nb][2] *= 0.125f; s[nb][3] *= 0.125f;
            mx0 = fmaxf(mx0, fmaxf(s[nb][0], s[nb][1]));
            mx1 = fmaxf(mx1, fmaxf(s[nb][2], s[nb][3]));
        }
        mx0 = fmaxf(mx0, __shfl_xor_sync(0xffffffffu, mx0, 1));
        mx0 = fmaxf(mx0, __shfl_xor_sync(0xffffffffu, mx0, 2));
        mx1 = fmaxf(mx1, __shfl_xor_sync(0xffffffffu, mx1, 1));
        mx1 = fmaxf(mx1, __shfl_xor_sync(0xffffffffu, mx1, 2));

        const float mn0 = fmaxf(m0, mx0);
        const float mn1 = fmaxf(m1, mx1);
        const float al0 = __expf(m0 - mn0);
        const float al1 = __expf(m1 - mn1);
        m0 = mn0; m1 = mn1;

        float rs0 = 0.0f, rs1 = 0.0f;
#pragma unroll
        for (int nb = 0; nb < 8; nb++) {
            s[nb][0] = __expf(s[nb][0] - m0);
            s[nb][1] = __expf(s[nb][1] - m0);
            s[nb][2] = __expf(s[nb][2] - m1);
            s[nb][3] = __expf(s[nb][3] - m1);
            rs0 += s[nb][0] + s[nb][1];
            rs1 += s[nb][2] + s[nb][3];
        }
        rs0 += __shfl_xor_sync(0xffffffffu, rs0, 1);
        rs0 += __shfl_xor_sync(0xffffffffu, rs0, 2);
        rs1 += __shfl_xor_sync(0xffffffffu, rs1, 1);
        rs1 += __shfl_xor_sync(0xffffffffu, rs1, 2);
        l0a = l0a * al0 + rs0;
        l1a = l1a * al1 + rs1;

#pragma unroll
        for (int nb = 0; nb < 8; nb++) {
            o[nb][0] *= al0; o[nb][1] *= al0;
            o[nb][2] *= al1; o[nb][3] *= al1;
        }

        // ---- O += P V ----
#pragma unroll
        for (int ks2 = 0; ks2 < 4; ks2++) {
            uint32_t pfh[4], pfl[4];
            split2(s[2 * ks2][0],     s[2 * ks2][1],     pfh[0], pfl[0]);
            split2(s[2 * ks2][2],     s[2 * ks2][3],     pfh[1], pfl[1]);
            split2(s[2 * ks2 + 1][0], s[2 * ks2 + 1][1], pfh[2], pfl[2]);
            split2(s[2 * ks2 + 1][2], s[2 * ks2 + 1][3], pfh[3], pfl[3]);
#pragma unroll
            for (int nb2 = 0; nb2 < 4; nb2++) {
                const uint32_t vb = st + 2 * KTB
                                  + (uint32_t)(ks2 * 16 * KROW)
                                  + (uint32_t)(nb2 * 32) + a_lm;
                uint32_t r0, r1, r2, r3, t0, t1, t2, t3;
                ldm_x4t(r0, r1, r2, r3, vb);
                ldm_x4t(t0, t1, t2, t3, vb + KTB);
                uint32_t vh0[2] = {r0, r1}, vh1[2] = {r2, r3};
                uint32_t vl0[2] = {t0, t1}, vl1[2] = {t2, t3};
                mma_bf16(o[2 * nb2],     pfh, vh0);
                mma_bf16(o[2 * nb2],     pfh, vl0);
                mma_bf16(o[2 * nb2],     pfl, vh0);
                mma_bf16(o[2 * nb2 + 1], pfh, vh1);
                mma_bf16(o[2 * nb2 + 1], pfh, vl1);
                mma_bf16(o[2 * nb2 + 1], pfl, vh1);
            }
        }
        __syncthreads();
    }

    // ---- epilogue: normalize, split, store blocked ao ----
    const float inv0 = 1.0f / l0a;
    const float inv1 = 1.0f / l1a;
    const int row0 = wid * 16 + (lane >> 2);
    const size_t tbase = ((size_t)(b * 8 + qt) * NKS + h) * TB;
#pragma unroll
    for (int nb = 0; nb < 8; nb++) {
        const int cc = (nb * 8 + (lane & 3) * 2) * 2;
        uint32_t hh, ll;
        split2(o[nb][0] * inv0, o[nb][1] * inv0, hh, ll);
        *(uint32_t*)(ah + tbase + (size_t)row0 * KROW + cc) = hh;
        *(uint32_t*)(al + tbase + (size_t)row0 * KROW + cc) = ll;
        split2(o[nb][2] * inv1, o[nb][3] * inv1, hh, ll);
        *(uint32_t*)(ah + tbase + (size_t)(row0 + 8) * KROW + cc) = hh;
        *(uint32_t*)(al + tbase + (size_t)(row0 + 8) * KROW + cc) = ll;
    }
}

// ===========================================================================
extern "C" void kernel_launch(void* const* d_in, const int* in_sizes, int n_in,
                              void* d_out, int out_size)
{
    const float* x      = (const float*)d_in[0];
    const float* w_qkv  = (const float*)d_in[1];
    const float* w_proj = (const float*)d_in[2];
    const float* b_proj = (const float*)d_in[3];
    float* out = (float*)d_out;

    char *xh, *xl, *wqh, *wql, *wph, *wpl, *qh, *ql, *ah, *al;
    cudaGetSymbolAddress((void**)&xh,  g_xhi);
    cudaGetSymbolAddress((void**)&xl,  g_xlo);
    cudaGetSymbolAddress((void**)&wqh, g_wqh);
    cudaGetSymbolAddress((void**)&wql, g_wql);
    cudaGetSymbolAddress((void**)&wph, g_wph);
    cudaGetSymbolAddress((void**)&wpl, g_wpl);
    cudaGetSymbolAddress((void**)&qh,  g_qh);
    cudaGetSymbolAddress((void**)&ql,  g_ql);
    cudaGetSymbolAddress((void**)&ah,  g_ah);
    cudaGetSymbolAddress((void**)&al,  g_al);

    cudaFuncSetAttribute(gemm_blk_kernel,
                         cudaFuncAttributeMaxDynamicSharedMemorySize, GSMEM);
    cudaFuncSetAttribute(attn_blk_kernel,
                         cudaFuncAttributeMaxDynamicSharedMemorySize, ASMEM);

    // 0) split + block inputs
    split_blk_kernel<<<M_TOK * DIM / 4 / 256, 256>>>(
        (const float4*)x, xh, xl, M_TOK * DIM / 4);
    split_blk_kernel<<<QKV_E * DIM / 4 / 256, 256>>>(
        (const float4*)w_qkv, wqh, wql, QKV_E * DIM / 4);
    split_blk_kernel<<<DIM * DIM / 4 / 256, 256>>>(
        (const float4*)w_proj, wph, wpl, DIM * DIM / 4);

    // 1) QKV projection -> blocked qkv (split)
    dim3 g1(QKV_E / 128, M_TOK / 128);   // (18, 128)
    gemm_blk_kernel<<<g1, 256, GSMEM>>>(xh, xl, wqh, wql,
                                        nullptr, nullptr, qh, ql, 0, 0);

    // 2) Attention -> blocked ao (split)
    dim3 g2(SEQ / 128, BATCH * NHEAD);   // (8, 192)
    attn_blk_kernel<<<g2, 256, ASMEM>>>(qh, ql, ah, al);

    // 3) Output projection -> fp32 out + bias
    dim3 g3(DIM / 128, M_TOK / 128);     // (6, 128)
    gemm_blk_kernel<<<g3, 256, GSMEM>>>(ah, al, wph, wpl,
                                        b_proj, out, nullptr, nullptr,
                                        DIM, 1);
}

// round 7
// speedup vs baseline: 1.2311x; 1.0683x over previous
#include <cuda_runtime.h>
#include <cuda_bf16.h>
#include <math.h>
#include <stdint.h>

#define BATCH 16
#define SEQ   1024
#define DIM   768
#define NHEAD 12
#define HDIM  64

#define M_TOK (BATCH * SEQ)      // 16384
#define QKV_E (3 * DIM)          // 2304

#define KROW 144                 // bytes per 64-bf16 row (128B data + 16B pad)
#define TB   (128 * KROW)        // 18432: 128-row tile
#define KTB  (64 * KROW)         // 9216:  64-row tile
#define NKS  (DIM / 64)          // 12 k-stages

// ----------------- blocked scratch (bf16 hi/lo, 144B-pitch tiles) ----------
__device__ __align__(128) char g_xhi[(size_t)128 * NKS * TB];
__device__ __align__(128) char g_xlo[(size_t)128 * NKS * TB];
__device__ __align__(128) char g_wqh[(size_t)18 * NKS * TB];
__device__ __align__(128) char g_wql[(size_t)18 * NKS * TB];
__device__ __align__(128) char g_wph[(size_t)6 * NKS * TB];
__device__ __align__(128) char g_wpl[(size_t)6 * NKS * TB];
// qkv blocked: [b][kind(3)][h][st(16)][KTB]
__device__ __align__(128) char g_qh[(size_t)BATCH * 3 * NHEAD * 16 * KTB];
__device__ __align__(128) char g_ql[(size_t)BATCH * 3 * NHEAD * 16 * KTB];
// ao blocked: [m_tile(128)][k_stage(12)][TB]
__device__ __align__(128) char g_ah[(size_t)128 * NKS * TB];
__device__ __align__(128) char g_al[(size_t)128 * NKS * TB];

// ----------------------------- helpers -------------------------------------
__device__ __forceinline__ uint32_t smem_u32(const void* p) {
    uint32_t a;
    asm("{ .reg .u64 t; cvta.to.shared.u64 t, %1; cvt.u32.u64 %0, t; }"
        : "=r"(a) : "l"(p));
    return a;
}

__device__ __forceinline__ void ldm_x4(uint32_t& r0, uint32_t& r1,
                                       uint32_t& r2, uint32_t& r3,
                                       uint32_t addr) {
    asm volatile("ldmatrix.sync.aligned.m8n8.x4.shared.b16 {%0,%1,%2,%3}, [%4];"
                 : "=r"(r0), "=r"(r1), "=r"(r2), "=r"(r3) : "r"(addr));
}

__device__ __forceinline__ void ldm_x4t(uint32_t& r0, uint32_t& r1,
                                        uint32_t& r2, uint32_t& r3,
                                        uint32_t addr) {
    asm volatile(
        "ldmatrix.sync.aligned.m8n8.x4.trans.shared.b16 {%0,%1,%2,%3}, [%4];"
        : "=r"(r0), "=r"(r1), "=r"(r2), "=r"(r3) : "r"(addr));
}

__device__ __forceinline__ void mma_bf16(float* c, const uint32_t* a,
                                         const uint32_t* b) {
    asm volatile(
        "mma.sync.aligned.m16n8k16.row.col.f32.bf16.bf16.f32 "
        "{%0,%1,%2,%3}, {%4,%5,%6,%7}, {%8,%9}, {%0,%1,%2,%3};"
        : "+f"(c[0]), "+f"(c[1]), "+f"(c[2]), "+f"(c[3])
        : "r"(a[0]), "r"(a[1]), "r"(a[2]), "r"(a[3]), "r"(b[0]), "r"(b[1]));
}

__device__ __forceinline__ void split2(float x, float y,
                                       uint32_t& hi, uint32_t& lo) {
    __nv_bfloat162 h = __floats2bfloat162_rn(x, y);
    __nv_bfloat162 l = __floats2bfloat162_rn(
        x - __bfloat162float(__low2bfloat16(h)),
        y - __bfloat162float(__high2bfloat16(h)));
    hi = *(uint32_t*)&h;
    lo = *(uint32_t*)&l;
}

__device__ __forceinline__ void mbar_init(uint32_t mb, uint32_t cnt) {
    asm volatile("mbarrier.init.shared.b64 [%0], %1;"
                 :: "r"(mb), "r"(cnt) : "memory");
}
__device__ __forceinline__ void mbar_expect(uint32_t mb, uint32_t bytes) {
    asm volatile("mbarrier.arrive.expect_tx.shared.b64 _, [%0], %1;"
                 :: "r"(mb), "r"(bytes) : "memory");
}
__device__ __forceinline__ void mbar_wait(uint32_t mb, uint32_t parity) {
    asm volatile(
        "{\n\t.reg .pred P;\n\t"
        "WL%=:\n\t"
        "mbarrier.try_wait.parity.acquire.cta.shared::cta.b64 P, [%0], %1, 0x989680;\n\t"
        "@P bra WD%=;\n\t"
        "bra WL%=;\n\t"
        "WD%=:\n\t}"
        :: "r"(mb), "r"(parity) : "memory");
}
__device__ __forceinline__ void bulkcp(uint32_t sdst, const void* gsrc,
                                       uint32_t bytes, uint32_t mb) {
    asm volatile(
        "cp.async.bulk.shared::cta.global.mbarrier::complete_tx::bytes "
        "[%0], [%1], %2, [%3];"
        :: "r"(sdst), "l"(gsrc), "r"(bytes), "r"(mb) : "memory");
}
__device__ __forceinline__ void bulkst(void* gdst, uint32_t ssrc,
                                       uint32_t bytes) {
    asm volatile(
        "cp.async.bulk.global.shared::cta.bulk_group [%0], [%1], %2;"
        :: "l"(gdst), "r"(ssrc), "r"(bytes) : "memory");
}
__device__ __forceinline__ void bulkst_flush() {
    asm volatile("cp.async.bulk.commit_group;" ::: "memory");
    asm volatile("cp.async.bulk.wait_group 0;" ::: "memory");
}

// ------------- fp32 [M,768] -> blocked split bf16 hi/lo tiles ---------------
__global__ void split_blk_kernel(const float4* __restrict__ src,
                                 char* __restrict__ hi, char* __restrict__ lo,
                                 int n4)
{
    int i = blockIdx.x * blockDim.x + threadIdx.x;
    if (i >= n4) return;
    int idx = i * 4;
    int m = idx / DIM;
    int e = idx - m * DIM;
    float4 v = src[i];
    uint32_t h0, h1, l0, l1;
    split2(v.x, v.y, h0, l0);
    split2(v.z, v.w, h1, l1);
    size_t off = ((size_t)(m >> 7) * NKS + (e >> 6)) * TB
               + (size_t)(m & 127) * KROW + (e & 63) * 2;
    *(uint2*)(hi + off) = make_uint2(h0, h1);
    *(uint2*)(lo + off) = make_uint2(l0, l1);
}

// ===========================================================================
// Bulk-DMA split-bf16 HMMA GEMM (NT), K=768, CTA 128x128, BK=64, 3-stage.
// mode 0: bulk-store blocked qkv (hi/lo). mode 1: fp32 C + bias.
// ===========================================================================
#define GSMEM (128 + 3 * 4 * TB)   // 221312

__global__ __launch_bounds__(256, 1) void gemm_blk_kernel(
    const char* __restrict__ Ahi, const char* __restrict__ Alo,
    const char* __restrict__ Bhi, const char* __restrict__ Blo,
    const float* __restrict__ bias, float* __restrict__ Cf,
    char* __restrict__ Qhi, char* __restrict__ Qlo,
    int Nn, int mode)
{
    extern __shared__ __align__(128) char smc[];
    const uint32_t sb = smem_u32(smc);
    const uint32_t bufs = sb + 128;

    const int tid = threadIdx.x;
    const int lane = tid & 31;
    const int wid = tid >> 5;
    const int wm = wid >> 2;
    const int wn = wid & 3;
    const int bx = blockIdx.x;
    const int by = blockIdx.y;

    if (tid == 0) { mbar_init(sb, 1); mbar_init(sb + 8, 1); mbar_init(sb + 16, 1); }
    __syncthreads();

    const char* Asrc[2] = {Ahi + (size_t)by * NKS * TB,
                           Alo + (size_t)by * NKS * TB};
    const char* Bsrc[2] = {Bhi + (size_t)bx * NKS * TB,
                           Blo + (size_t)bx * NKS * TB};

    if (tid == 0) {
#pragma unroll
        for (int s = 0; s < 2; s++) {
            const uint32_t mb = sb + s * 8;
            const uint32_t bu = bufs + s * 4 * TB;
            const size_t go = (size_t)s * TB;
            mbar_expect(mb, 4 * TB);
            bulkcp(bu + 0 * TB, Asrc[0] + go, TB, mb);
            bulkcp(bu + 1 * TB, Asrc[1] + go, TB, mb);
            bulkcp(bu + 2 * TB, Bsrc[0] + go, TB, mb);
            bulkcp(bu + 3 * TB, Bsrc[1] + go, TB, mb);
        }
    }

    const uint32_t a_lm = (uint32_t)((lane & 15) * KROW + (lane >> 4) * 16
                        + wm * 64 * KROW);
    const uint32_t b_lm = (uint32_t)((((lane >> 4) << 3) + (lane & 7)) * KROW
                        + ((lane >> 3) & 1) * 16 + wn * 32 * KROW);

    float c[4][4][4];
#pragma unroll
    for (int i = 0; i < 4; i++)
#pragma unroll
        for (int j = 0; j < 4; j++)
#pragma unroll
            for (int q = 0; q < 4; q++) c[i][j][q] = 0.0f;

    uint32_t ph3[3] = {0, 0, 0};

    for (int ic = 0; ic < NKS; ic++) {
        __syncthreads();   // all warps done with stage ic-1 buffer

        if (tid == 0 && ic + 2 < NKS) {
            const int b2 = (ic + 2) % 3;
            const uint32_t mb = sb + b2 * 8;
            const uint32_t bu = bufs + (uint32_t)(b2 * 4 * TB);
            const size_t go = (size_t)(ic + 2) * TB;
            mbar_expect(mb, 4 * TB);
            bulkcp(bu + 0 * TB, Asrc[0] + go, TB, mb);
            bulkcp(bu + 1 * TB, Asrc[1] + go, TB, mb);
            bulkcp(bu + 2 * TB, Bsrc[0] + go, TB, mb);
            bulkcp(bu + 3 * TB, Bsrc[1] + go, TB, mb);
        }

        const int bs = ic % 3;
        mbar_wait(sb + bs * 8, ph3[bs]);
        ph3[bs] ^= 1;

        const uint32_t su = bufs + (uint32_t)(bs * 4 * TB);
#pragma unroll
        for (int ks = 0; ks < 4; ks++) {
            const uint32_t kofs = (uint32_t)(ks * 32);
            uint32_t ah[4][4], al[4][4], bh[4][2], bl[4][2];
#pragma unroll
            for (int im = 0; im < 4; im++) {
                uint32_t base = su + a_lm + (uint32_t)(im * 16 * KROW) + kofs;
                ldm_x4(ah[im][0], ah[im][1], ah[im][2], ah[im][3], base);
                ldm_x4(al[im][0], al[im][1], al[im][2], al[im][3], base + TB);
            }
#pragma unroll
            for (int in2 = 0; in2 < 2; in2++) {
                uint32_t base = su + 2 * TB + b_lm
                              + (uint32_t)(in2 * 16 * KROW) + kofs;
                uint32_t r0, r1, r2, r3;
                ldm_x4(r0, r1, r2, r3, base);
                bh[in2 * 2][0] = r0; bh[in2 * 2][1] = r1;
                bh[in2 * 2 + 1][0] = r2; bh[in2 * 2 + 1][1] = r3;
                ldm_x4(r0, r1, r2, r3, base + TB);
                bl[in2 * 2][0] = r0; bl[in2 * 2][1] = r1;
                bl[in2 * 2 + 1][0] = r2; bl[in2 * 2 + 1][1] = r3;
            }
            // term-major order: 16 independent accumulators between reuses
#pragma unroll
            for (int t = 0; t < 3; t++)
#pragma unroll
                for (int im = 0; im < 4; im++)
#pragma unroll
                    for (int inn = 0; inn < 4; inn++)
                        mma_bf16(c[im][inn],
                                 (t == 2) ? al[im] : ah[im],
                                 (t == 1) ? bl[inn] : bh[inn]);
        }
    }

    if (mode == 1) {
#pragma unroll
        for (int im = 0; im < 4; im++) {
            const size_t row = (size_t)by * 128 + wm * 64 + im * 16 + (lane >> 2);
#pragma unroll
            for (int inn = 0; inn < 4; inn++) {
                const int col = bx * 128 + wn * 32 + inn * 8 + (lane & 3) * 2;
                float b0 = bias[col], b1 = bias[col + 1];
                *(float2*)(Cf + row * Nn + col) =
                    make_float2(c[im][inn][0] + b0, c[im][inn][1] + b1);
                *(float2*)(Cf + (row + 8) * Nn + col) =
                    make_float2(c[im][inn][2] + b0, c[im][inn][3] + b1);
            }
        }
    } else {
        // stage split output in buf0 (free: last used at stage 9), bulk-store
        char* stg = smc + 128;
#pragma unroll
        for (int im = 0; im < 4; im++) {
            const int r0 = wm * 64 + im * 16 + (lane >> 2);
#pragma unroll
            for (int inn = 0; inn < 4; inn++) {
                const int el = wn * 32 + inn * 8 + (lane & 3) * 2;
                const int eg = el >> 6;
                const int cc = (el & 63) * 2;
                uint32_t h, l;
                split2(c[im][inn][0], c[im][inn][1], h, l);
                *(uint32_t*)(stg + (size_t)(eg * 2 + 0) * TB + r0 * KROW + cc) = h;
                *(uint32_t*)(stg + (size_t)(eg * 2 + 1) * TB + r0 * KROW + cc) = l;
                split2(c[im][inn][2], c[im][inn][3], h, l);
                *(uint32_t*)(stg + (size_t)(eg * 2 + 0) * TB + (r0 + 8) * KROW + cc) = h;
                *(uint32_t*)(stg + (size_t)(eg * 2 + 1) * TB + (r0 + 8) * KROW + cc) = l;
            }
        }
        __syncthreads();
        if (tid == 0) {
            asm volatile("fence.proxy.async.shared::cta;" ::: "memory");
            const int bq = by >> 3;
#pragma unroll
            for (int eg = 0; eg < 2; eg++) {
                const int g = bx * 2 + eg;
                const int kind = g / 12;
                const int hh = g - kind * 12;
                const size_t dst = ((size_t)((bq * 3 + kind) * 12 + hh)) * (16 * KTB)
                                 + (size_t)(by & 7) * TB;
                bulkst(Qhi + dst, bufs + (uint32_t)((eg * 2 + 0) * TB), TB);
                bulkst(Qlo + dst, bufs + (uint32_t)((eg * 2 + 1) * TB), TB);
            }
            bulkst_flush();
        }
        __syncthreads();
    }
}

// ===========================================================================
// Flash attention: 128-query x 128-key tiles, split-bf16 HMMA,
// bulk-DMA K/V double buffer, bulk-store epilogue.
// ===========================================================================
#define AQ    128
#define AKV0  (AQ + 2 * TB)
#define ASTG  (4 * TB)                    // Khi,Klo,Vhi,Vlo (128 rows each)
#define ASMEM (AKV0 + 2 * ASTG)           // 184448

__global__ __launch_bounds__(256, 1) void attn_blk_kernel(
    const char* __restrict__ qh, const char* __restrict__ ql,
    char* __restrict__ ah, char* __restrict__ al)
{
    extern __shared__ __align__(128) char smc[];
    const uint32_t sb = smem_u32(smc);

    const int tid = threadIdx.x;
    const int lane = tid & 31;
    const int wid = tid >> 5;

    const int qt = blockIdx.x;        // 0..7
    const int bh = blockIdx.y;        // 0..191
    const int b = bh / NHEAD;
    const int h = bh % NHEAD;

    const size_t baseQ = ((size_t)((b * 3 + 0) * 12 + h)) * (16 * KTB);
    const size_t baseK = ((size_t)((b * 3 + 1) * 12 + h)) * (16 * KTB);
    const size_t baseV = ((size_t)((b * 3 + 2) * 12 + h)) * (16 * KTB);

    if (tid == 0) {
        mbar_init(sb, 1); mbar_init(sb + 8, 1); mbar_init(sb + 16, 1);
    }
    __syncthreads();

    if (tid == 0) {
        mbar_expect(sb, 2 * TB);
        bulkcp(sb + AQ,      qh + baseQ + (size_t)qt * TB, TB, sb);
        bulkcp(sb + AQ + TB, ql + baseQ + (size_t)qt * TB, TB, sb);
        mbar_expect(sb + 8, ASTG);
        bulkcp(sb + AKV0 + 0 * TB, qh + baseK, TB, sb + 8);
        bulkcp(sb + AKV0 + 1 * TB, ql + baseK, TB, sb + 8);
        bulkcp(sb + AKV0 + 2 * TB, qh + baseV, TB, sb + 8);
        bulkcp(sb + AKV0 + 3 * TB, ql + baseV, TB, sb + 8);
    }

    const uint32_t a_lm = (uint32_t)((lane & 15) * KROW + (lane >> 4) * 16);
    const uint32_t b_lm = (uint32_t)((((lane >> 4) << 3) + (lane & 7)) * KROW
                        + ((lane >> 3) & 1) * 16);

    uint32_t qfh[4][4], qfl[4][4];

    float m0 = -INFINITY, m1 = -INFINITY, l0a = 0.0f, l1a = 0.0f;
    float o[8][4];
#pragma unroll
    for (int nb = 0; nb < 8; nb++)
#pragma unroll
        for (int q = 0; q < 4; q++) o[nb][q] = 0.0f;

    uint32_t ph[2] = {0, 0};

    for (int jt = 0; jt < SEQ / 128; jt++) {     // 8 iterations
        __syncthreads();   // all done with buffer being overwritten

        if (tid == 0 && jt + 1 < SEQ / 128) {
            const uint32_t mb = sb + 8 + ((jt + 1) & 1) * 8;
            const uint32_t bu = sb + AKV0 + ((jt + 1) & 1) * ASTG;
            const size_t go = (size_t)(jt + 1) * TB;
            mbar_expect(mb, ASTG);
            bulkcp(bu + 0 * TB, qh + baseK + go, TB, mb);
            bulkcp(bu + 1 * TB, ql + baseK + go, TB, mb);
            bulkcp(bu + 2 * TB, qh + baseV + go, TB, mb);
            bulkcp(bu + 3 * TB, ql + baseV + go, TB, mb);
        }
        const int bs = jt & 1;
        mbar_wait(sb + 8 + bs * 8, ph[bs]);
        ph[bs] ^= 1;

        if (jt == 0) {
            mbar_wait(sb, 0);
            const uint32_t qbase = sb + AQ + (uint32_t)(wid * 16 * KROW) + a_lm;
#pragma unroll
            for (int ks = 0; ks < 4; ks++) {
                ldm_x4(qfh[ks][0], qfh[ks][1], qfh[ks][2], qfh[ks][3],
                       qbase + ks * 32);
                ldm_x4(qfl[ks][0], qfl[ks][1], qfl[ks][2], qfl[ks][3],
                       qbase + TB + ks * 32);
            }
        }

        const uint32_t st = sb + AKV0 + (uint32_t)(bs * ASTG);

        // ---- S = Q K^T over 128 keys, 3-term split ----
        float s[16][4];
#pragma unroll
        for (int nb = 0; nb < 16; nb++)
#pragma unroll
            for (int q = 0; q < 4; q++) s[nb][q] = 0.0f;

#pragma unroll
        for (int ks = 0; ks < 4; ks++) {
#pragma unroll
            for (int nb2 = 0; nb2 < 8; nb2++) {
                const uint32_t kb = st + (uint32_t)(nb2 * 16 * KROW)
                                  + b_lm + ks * 32;
                uint32_t r0, r1, r2, r3, t0, t1, t2, t3;
                ldm_x4(r0, r1, r2, r3, kb);
                ldm_x4(t0, t1, t2, t3, kb + TB);
                uint32_t bh0[2] = {r0, r1}, bh1[2] = {r2, r3};
                uint32_t bl0[2] = {t0, t1}, bl1[2] = {t2, t3};
                mma_bf16(s[2 * nb2],     qfh[ks], bh0);
                mma_bf16(s[2 * nb2 + 1], qfh[ks], bh1);
                mma_bf16(s[2 * nb2],     qfh[ks], bl0);
                mma_bf16(s[2 * nb2 + 1], qfh[ks], bl1);
                mma_bf16(s[2 * nb2],     qfl[ks], bh0);
                mma_bf16(s[2 * nb2 + 1], qfl[ks], bh1);
            }
        }

        // ---- online softmax (128 keys at once) ----
        float mx0 = -INFINITY, mx1 = -INFINITY;
#pragma unroll
        for (int nb = 0; nb < 16; nb++) {
            s[nb][0] *= 0.125f; s[nb][1] *= 0.125f;
            s[nb][2] *= 0.125f; s[nb][3] *= 0.125f;
            mx0 = fmaxf(mx0, fmaxf(s[nb][0], s[nb][1]));
            mx1 = fmaxf(mx1, fmaxf(s[nb][2], s[nb][3]));
        }
        mx0 = fmaxf(mx0, __shfl_xor_sync(0xffffffffu, mx0, 1));
        mx0 = fmaxf(mx0, __shfl_xor_sync(0xffffffffu, mx0, 2));
        mx1 = fmaxf(mx1, __shfl_xor_sync(0xffffffffu, mx1, 1));
        mx1 = fmaxf(mx1, __shfl_xor_sync(0xffffffffu, mx1, 2));

        const float mn0 = fmaxf(m0, mx0);
        const float mn1 = fmaxf(m1, mx1);
        const float al0 = __expf(m0 - mn0);
        const float al1 = __expf(m1 - mn1);
        m0 = mn0; m1 = mn1;

        float rs0 = 0.0f, rs1 = 0.0f;
#pragma unroll
        for (int nb = 0; nb < 16; nb++) {
            s[nb][0] = __expf(s[nb][0] - m0);
            s[nb][1] = __expf(s[nb][1] - m0);
            s[nb][2] = __expf(s[nb][2] - m1);
            s[nb][3] = __expf(s[nb][3] - m1);
            rs0 += s[nb][0] + s[nb][1];
            rs1 += s[nb][2] + s[nb][3];
        }
        rs0 += __shfl_xor_sync(0xffffffffu, rs0, 1);
        rs0 += __shfl_xor_sync(0xffffffffu, rs0, 2);
        rs1 += __shfl_xor_sync(0xffffffffu, rs1, 1);
        rs1 += __shfl_xor_sync(0xffffffffu, rs1, 2);
        l0a = l0a * al0 + rs0;
        l1a = l1a * al1 + rs1;

#pragma unroll
        for (int nb = 0; nb < 8; nb++) {
            o[nb][0] *= al0; o[nb][1] *= al0;
            o[nb][2] *= al1; o[nb][3] *= al1;
        }

        // ---- O += P V over 128 keys (P split in regs; V via ldm.trans) ----
#pragma unroll
        for (int ks2 = 0; ks2 < 8; ks2++) {
            uint32_t pfh[4], pfl[4];
            split2(s[2 * ks2][0],     s[2 * ks2][1],     pfh[0], pfl[0]);
            split2(s[2 * ks2][2],     s[2 * ks2][3],     pfh[1], pfl[1]);
            split2(s[2 * ks2 + 1][0], s[2 * ks2 + 1][1], pfh[2], pfl[2]);
            split2(s[2 * ks2 + 1][2], s[2 * ks2 + 1][3], pfh[3], pfl[3]);
#pragma unroll
            for (int nb2 = 0; nb2 < 4; nb2++) {
                const uint32_t vb = st + 2 * TB
                                  + (uint32_t)(ks2 * 16 * KROW)
                                  + (uint32_t)(nb2 * 32) + a_lm;
                uint32_t r0, r1, r2, r3, t0, t1, t2, t3;
                ldm_x4t(r0, r1, r2, r3, vb);
                ldm_x4t(t0, t1, t2, t3, vb + TB);
                uint32_t vh0[2] = {r0, r1}, vh1[2] = {r2, r3};
                uint32_t vl0[2] = {t0, t1}, vl1[2] = {t2, t3};
                mma_bf16(o[2 * nb2],     pfh, vh0);
                mma_bf16(o[2 * nb2 + 1], pfh, vh1);
                mma_bf16(o[2 * nb2],     pfh, vl0);
                mma_bf16(o[2 * nb2 + 1], pfh, vl1);
                mma_bf16(o[2 * nb2],     pfl, vh0);
                mma_bf16(o[2 * nb2 + 1], pfl, vh1);
            }
        }
    }

    // ---- epilogue: normalize, split, stage into Q buffer, bulk-store ----
    const float inv0 = 1.0f / l0a;
    const float inv1 = 1.0f / l1a;
    const int row0 = wid * 16 + (lane >> 2);
#pragma unroll
    for (int nb = 0; nb < 8; nb++) {
        const int cc = (nb * 8 + (lane & 3) * 2) * 2;
        uint32_t hh, ll;
        split2(o[nb][0] * inv0, o[nb][1] * inv0, hh, ll);
        *(uint32_t*)(smc + AQ + row0 * KROW + cc) = hh;
        *(uint32_t*)(smc + AQ + TB + row0 * KROW + cc) = ll;
        split2(o[nb][2] * inv1, o[nb][3] * inv1, hh, ll);
        *(uint32_t*)(smc + AQ + (row0 + 8) * KROW + cc) = hh;
        *(uint32_t*)(smc + AQ + TB + (row0 + 8) * KROW + cc) = ll;
    }
    __syncthreads();
    if (tid == 0) {
        asm volatile("fence.proxy.async.shared::cta;" ::: "memory");
        const size_t tbase = ((size_t)(b * 8 + qt) * NKS + h) * TB;
        bulkst(ah + tbase, sb + AQ, TB);
        bulkst(al + tbase, sb + AQ + TB, TB);
        bulkst_flush();
    }
    __syncthreads();
}

// ===========================================================================
extern "C" void kernel_launch(void* const* d_in, const int* in_sizes, int n_in,
                              void* d_out, int out_size)
{
    const float* x      = (const float*)d_in[0];
    const float* w_qkv  = (const float*)d_in[1];
    const float* w_proj = (const float*)d_in[2];
    const float* b_proj = (const float*)d_in[3];
    float* out = (float*)d_out;

    char *xh, *xl, *wqh, *wql, *wph, *wpl, *qh, *ql, *ah, *al;
    cudaGetSymbolAddress((void**)&xh,  g_xhi);
    cudaGetSymbolAddress((void**)&xl,  g_xlo);
    cudaGetSymbolAddress((void**)&wqh, g_wqh);
    cudaGetSymbolAddress((void**)&wql, g_wql);
    cudaGetSymbolAddress((void**)&wph, g_wph);
    cudaGetSymbolAddress((void**)&wpl, g_wpl);
    cudaGetSymbolAddress((void**)&qh,  g_qh);
    cudaGetSymbolAddress((void**)&ql,  g_ql);
    cudaGetSymbolAddress((void**)&ah,  g_ah);
    cudaGetSymbolAddress((void**)&al,  g_al);

    cudaFuncSetAttribute(gemm_blk_kernel,
                         cudaFuncAttributeMaxDynamicSharedMemorySize, GSMEM);
    cudaFuncSetAttribute(attn_blk_kernel,
                         cudaFuncAttributeMaxDynamicSharedMemorySize, ASMEM);

    // 0) split + block inputs
    split_blk_kernel<<<M_TOK * DIM / 4 / 256, 256>>>(
        (const float4*)x, xh, xl, M_TOK * DIM / 4);
    split_blk_kernel<<<QKV_E * DIM / 4 / 256, 256>>>(
        (const float4*)w_qkv, wqh, wql, QKV_E * DIM / 4);
    split_blk_kernel<<<DIM * DIM / 4 / 256, 256>>>(
        (const float4*)w_proj, wph, wpl, DIM * DIM / 4);

    // 1) QKV projection -> blocked qkv (split)
    dim3 g1(QKV_E / 128, M_TOK / 128);   // (18, 128)
    gemm_blk_kernel<<<g1, 256, GSMEM>>>(xh, xl, wqh, wql,
                                        nullptr, nullptr, qh, ql, 0, 0);

    // 2) Attention -> blocked ao (split)
    dim3 g2(SEQ / 128, BATCH * NHEAD);   // (8, 192)
    attn_blk_kernel<<<g2, 256, ASMEM>>>(qh, ql, ah, al);

    // 3) Output projection -> fp32 out + bias
    dim3 g3(DIM / 128, M_TOK / 128);     // (6, 128)
    gemm_blk_kernel<<<g3, 256, GSMEM>>>(ah, al, wph, wpl,
                                        b_proj, out, nullptr, nullptr,
                                        DIM, 1);
}

// round 9
// speedup vs baseline: 1.2637x; 1.0265x over previous
#include <cuda_runtime.h>
#include <cuda_bf16.h>
#include <math.h>
#include <stdint.h>

#define BATCH 16
#define SEQ   1024
#define DIM   768
#define NHEAD 12
#define HDIM  64

#define M_TOK (BATCH * SEQ)      // 16384
#define QKV_E (3 * DIM)          // 2304

#define KROW 144                 // bytes per 64-bf16 row (128B data + 16B pad)
#define TB   (128 * KROW)        // 18432: 128-row tile
#define KTB  (64 * KROW)         // 9216:  64-row tile
#define NKS  (DIM / 64)          // 12 k-stages

// ----------------- blocked scratch (bf16 hi/lo, 144B-pitch tiles) ----------
__device__ __align__(128) char g_xhi[(size_t)128 * NKS * TB];
__device__ __align__(128) char g_xlo[(size_t)128 * NKS * TB];
__device__ __align__(128) char g_wqh[(size_t)18 * NKS * TB];
__device__ __align__(128) char g_wql[(size_t)18 * NKS * TB];
__device__ __align__(128) char g_wph[(size_t)6 * NKS * TB];
__device__ __align__(128) char g_wpl[(size_t)6 * NKS * TB];
// qkv blocked: [b][kind(3)][h][st(16)][KTB]
__device__ __align__(128) char g_qh[(size_t)BATCH * 3 * NHEAD * 16 * KTB];
__device__ __align__(128) char g_ql[(size_t)BATCH * 3 * NHEAD * 16 * KTB];
// ao blocked: [m_tile(128)][k_stage(12)][TB]
__device__ __align__(128) char g_ah[(size_t)128 * NKS * TB];
__device__ __align__(128) char g_al[(size_t)128 * NKS * TB];

// ----------------------------- helpers -------------------------------------
__device__ __forceinline__ uint32_t smem_u32(const void* p) {
    uint32_t a;
    asm("{ .reg .u64 t; cvta.to.shared.u64 t, %1; cvt.u32.u64 %0, t; }"
        : "=r"(a) : "l"(p));
    return a;
}

__device__ __forceinline__ void ldm_x4(uint32_t& r0, uint32_t& r1,
                                       uint32_t& r2, uint32_t& r3,
                                       uint32_t addr) {
    asm volatile("ldmatrix.sync.aligned.m8n8.x4.shared.b16 {%0,%1,%2,%3}, [%4];"
                 : "=r"(r0), "=r"(r1), "=r"(r2), "=r"(r3) : "r"(addr));
}

__device__ __forceinline__ void ldm_x4t(uint32_t& r0, uint32_t& r1,
                                        uint32_t& r2, uint32_t& r3,
                                        uint32_t addr) {
    asm volatile(
        "ldmatrix.sync.aligned.m8n8.x4.trans.shared.b16 {%0,%1,%2,%3}, [%4];"
        : "=r"(r0), "=r"(r1), "=r"(r2), "=r"(r3) : "r"(addr));
}

__device__ __forceinline__ void mma_bf16(float* c, const uint32_t* a,
                                         const uint32_t* b) {
    asm volatile(
        "mma.sync.aligned.m16n8k16.row.col.f32.bf16.bf16.f32 "
        "{%0,%1,%2,%3}, {%4,%5,%6,%7}, {%8,%9}, {%0,%1,%2,%3};"
        : "+f"(c[0]), "+f"(c[1]), "+f"(c[2]), "+f"(c[3])
        : "r"(a[0]), "r"(a[1]), "r"(a[2]), "r"(a[3]), "r"(b[0]), "r"(b[1]));
}

__device__ __forceinline__ void split2(float x, float y,
                                       uint32_t& hi, uint32_t& lo) {
    __nv_bfloat162 h = __floats2bfloat162_rn(x, y);
    __nv_bfloat162 l = __floats2bfloat162_rn(
        x - __bfloat162float(__low2bfloat16(h)),
        y - __bfloat162float(__high2bfloat16(h)));
    hi = *(uint32_t*)&h;
    lo = *(uint32_t*)&l;
}

__device__ __forceinline__ void mbar_init(uint32_t mb, uint32_t cnt) {
    asm volatile("mbarrier.init.shared.b64 [%0], %1;"
                 :: "r"(mb), "r"(cnt) : "memory");
}
__device__ __forceinline__ void mbar_expect(uint32_t mb, uint32_t bytes) {
    asm volatile("mbarrier.arrive.expect_tx.shared.b64 _, [%0], %1;"
                 :: "r"(mb), "r"(bytes) : "memory");
}
__device__ __forceinline__ void mbar_wait(uint32_t mb, uint32_t parity) {
    asm volatile(
        "{\n\t.reg .pred P;\n\t"
        "WL%=:\n\t"
        "mbarrier.try_wait.parity.acquire.cta.shared::cta.b64 P, [%0], %1, 0x989680;\n\t"
        "@P bra WD%=;\n\t"
        "bra WL%=;\n\t"
        "WD%=:\n\t}"
        :: "r"(mb), "r"(parity) : "memory");
}
__device__ __forceinline__ void bulkcp(uint32_t sdst, const void* gsrc,
                                       uint32_t bytes, uint32_t mb) {
    asm volatile(
        "cp.async.bulk.shared::cta.global.mbarrier::complete_tx::bytes "
        "[%0], [%1], %2, [%3];"
        :: "r"(sdst), "l"(gsrc), "r"(bytes), "r"(mb) : "memory");
}
__device__ __forceinline__ void bulkst(void* gdst, uint32_t ssrc,
                                       uint32_t bytes) {
    asm volatile(
        "cp.async.bulk.global.shared::cta.bulk_group [%0], [%1], %2;"
        :: "l"(gdst), "r"(ssrc), "r"(bytes) : "memory");
}
__device__ __forceinline__ void bulkst_flush() {
    asm volatile("cp.async.bulk.commit_group;" ::: "memory");
    asm volatile("cp.async.bulk.wait_group 0;" ::: "memory");
}

// ------------- fp32 [M,768] -> blocked split bf16 hi/lo tiles ---------------
__global__ void split_blk_kernel(const float4* __restrict__ src,
                                 char* __restrict__ hi, char* __restrict__ lo,
                                 int n4)
{
    int i = blockIdx.x * blockDim.x + threadIdx.x;
    if (i >= n4) return;
    int idx = i * 4;
    int m = idx / DIM;
    int e = idx - m * DIM;
    float4 v = src[i];
    uint32_t h0, h1, l0, l1;
    split2(v.x, v.y, h0, l0);
    split2(v.z, v.w, h1, l1);
    size_t off = ((size_t)(m >> 7) * NKS + (e >> 6)) * TB
               + (size_t)(m & 127) * KROW + (e & 63) * 2;
    *(uint2*)(hi + off) = make_uint2(h0, h1);
    *(uint2*)(lo + off) = make_uint2(l0, l1);
}

// ===========================================================================
// Bulk-DMA split-bf16 HMMA GEMM (NT), K=768, CTA 128x256, 512 thr, BK=64,
// 2-stage. 16 warps: wm=wid&7 (16-row slab), wn=wid>>3 (128-col half).
// mode 0: bulk-store blocked qkv (hi/lo). mode 1: fp32 C + bias.
// stage layout: [Ahi][Alo][Bhi0][Bhi1][Blo0][Blo1], each TB.
// ===========================================================================
#define GSTG  (6 * TB)            // 110592
#define GSMEM (128 + 2 * GSTG)    // 221312

__global__ __launch_bounds__(512, 1) void gemm_blk_kernel(
    const char* __restrict__ Ahi, const char* __restrict__ Alo,
    const char* __restrict__ Bhi, const char* __restrict__ Blo,
    const float* __restrict__ bias, float* __restrict__ Cf,
    char* __restrict__ Qhi, char* __restrict__ Qlo,
    int Nn, int mode)
{
    extern __shared__ __align__(128) char smc[];
    const uint32_t sb = smem_u32(smc);
    const uint32_t bufs = sb + 128;

    const int tid = threadIdx.x;
    const int lane = tid & 31;
    const int wid = tid >> 5;
    const int wm = wid & 7;           // 16-row slab
    const int wn = wid >> 3;          // 0..1: 128-col half = one B tile
    const int bx = blockIdx.x;
    const int by = blockIdx.y;

    if (tid == 0) { mbar_init(sb, 1); mbar_init(sb + 8, 1); }
    __syncthreads();

    const char* As[2] = {Ahi + (size_t)by * NKS * TB,
                         Alo + (size_t)by * NKS * TB};
    const char* Bs[4] = {Bhi + (size_t)(2 * bx) * NKS * TB,
                         Bhi + (size_t)(2 * bx + 1) * NKS * TB,
                         Blo + (size_t)(2 * bx) * NKS * TB,
                         Blo + (size_t)(2 * bx + 1) * NKS * TB};

    if (tid == 0) {
        mbar_expect(sb, GSTG);
        bulkcp(bufs + 0 * TB, As[0], TB, sb);
        bulkcp(bufs + 1 * TB, As[1], TB, sb);
        bulkcp(bufs + 2 * TB, Bs[0], TB, sb);
        bulkcp(bufs + 3 * TB, Bs[1], TB, sb);
        bulkcp(bufs + 4 * TB, Bs[2], TB, sb);
        bulkcp(bufs + 5 * TB, Bs[3], TB, sb);
    }

    const uint32_t a_lm = (uint32_t)((lane & 15) * KROW + (lane >> 4) * 16
                        + wm * 16 * KROW);
    const uint32_t b_lm = (uint32_t)((((lane >> 4) << 3) + (lane & 7)) * KROW
                        + ((lane >> 3) & 1) * 16);

    float c[16][4];
#pragma unroll
    for (int i = 0; i < 16; i++)
#pragma unroll
        for (int q = 0; q < 4; q++) c[i][q] = 0.0f;

    uint32_t ph[2] = {0, 0};

    for (int ic = 0; ic < NKS; ic++) {
        __syncthreads();   // all warps done with the buffer being overwritten

        if (tid == 0 && ic + 1 < NKS) {
            const uint32_t mb = sb + ((ic + 1) & 1) * 8;
            const uint32_t bu = bufs + ((ic + 1) & 1) * GSTG;
            const size_t go = (size_t)(ic + 1) * TB;
            mbar_expect(mb, GSTG);
            bulkcp(bu + 0 * TB, As[0] + go, TB, mb);
            bulkcp(bu + 1 * TB, As[1] + go, TB, mb);
            bulkcp(bu + 2 * TB, Bs[0] + go, TB, mb);
            bulkcp(bu + 3 * TB, Bs[1] + go, TB, mb);
            bulkcp(bu + 4 * TB, Bs[2] + go, TB, mb);
            bulkcp(bu + 5 * TB, Bs[3] + go, TB, mb);
        }

        const int bs = ic & 1;
        mbar_wait(sb + bs * 8, ph[bs]);
        ph[bs] ^= 1;

        const uint32_t su = bufs + (uint32_t)(bs * GSTG);
        const uint32_t bth = su + (uint32_t)((2 + wn) * TB) + b_lm;
        const uint32_t btl = su + (uint32_t)((4 + wn) * TB) + b_lm;

#pragma unroll
        for (int ks = 0; ks < 4; ks++) {
            const uint32_t kofs = (uint32_t)(ks * 32);
            uint32_t ah[4], al[4];
            ldm_x4(ah[0], ah[1], ah[2], ah[3], su + a_lm + kofs);
            ldm_x4(al[0], al[1], al[2], al[3], su + TB + a_lm + kofs);

#pragma unroll
            for (int g = 0; g < 2; g++) {        // 8 accumulators per group
                uint32_t bh[8][2], bl[8][2];
#pragma unroll
                for (int q = 0; q < 4; q++) {
                    uint32_t r0, r1, r2, r3;
                    const uint32_t ro = (uint32_t)((g * 4 + q) * 16 * KROW) + kofs;
                    ldm_x4(r0, r1, r2, r3, bth + ro);
                    bh[q * 2][0] = r0; bh[q * 2][1] = r1;
                    bh[q * 2 + 1][0] = r2; bh[q * 2 + 1][1] = r3;
                    ldm_x4(r0, r1, r2, r3, btl + ro);
                    bl[q * 2][0] = r0; bl[q * 2][1] = r1;
                    bl[q * 2 + 1][0] = r2; bl[q * 2 + 1][1] = r3;
                }
                // term-major: same-acc reuse gap = 8
#pragma unroll
                for (int t = 0; t < 3; t++)
#pragma unroll
                    for (int j = 0; j < 8; j++)
                        mma_bf16(c[g * 8 + j],
                                 (t == 2) ? al : ah,
                                 (t == 1) ? bl[j] : bh[j]);
            }
        }
    }

    if (mode == 1) {
#pragma unroll
        for (int j = 0; j < 16; j++) {
            const size_t row = (size_t)by * 128 + wm * 16 + (lane >> 2);
            const int col = bx * 256 + wn * 128 + j * 8 + (lane & 3) * 2;
            float b0 = bias[col], b1 = bias[col + 1];
            *(float2*)(Cf + row * Nn + col) =
                make_float2(c[j][0] + b0, c[j][1] + b1);
            *(float2*)(Cf + (row + 8) * Nn + col) =
                make_float2(c[j][2] + b0, c[j][3] + b1);
        }
    } else {
        // RACE FIX (round 8 bug): the staging region spans 8 tiles, which
        // overlaps stage-1's A tiles still being read by slower warps in the
        // final main-loop iteration. Synchronize before overwriting.
        __syncthreads();
        // stage split output: 8 tiles [cg(4)][hi/lo], then bulk-store
        char* stg = smc + 128;
        const int r0 = wm * 16 + (lane >> 2);
#pragma unroll
        for (int j = 0; j < 16; j++) {
            const int el = wn * 128 + j * 8 + (lane & 3) * 2;   // 0..255
            const int cg = el >> 6;
            const int cc = (el & 63) * 2;
            char* th = stg + (size_t)(cg * 2 + 0) * TB;
            char* tl = stg + (size_t)(cg * 2 + 1) * TB;
            uint32_t h, l;
            split2(c[j][0], c[j][1], h, l);
            *(uint32_t*)(th + r0 * KROW + cc) = h;
            *(uint32_t*)(tl + r0 * KROW + cc) = l;
            split2(c[j][2], c[j][3], h, l);
            *(uint32_t*)(th + (r0 + 8) * KROW + cc) = h;
            *(uint32_t*)(tl + (r0 + 8) * KROW + cc) = l;
        }
        __syncthreads();
        if (tid == 0) {
            asm volatile("fence.proxy.async.shared::cta;" ::: "memory");
            const int bq = by >> 3;
#pragma unroll
            for (int cg = 0; cg < 4; cg++) {
                const int g = bx * 4 + cg;
                const int kind = g / 12;
                const int hh = g - kind * 12;
                const size_t dst = ((size_t)((bq * 3 + kind) * 12 + hh)) * (16 * KTB)
                                 + (size_t)(by & 7) * TB;
                bulkst(Qhi + dst, bufs + (uint32_t)((cg * 2 + 0) * TB), TB);
                bulkst(Qlo + dst, bufs + (uint32_t)((cg * 2 + 1) * TB), TB);
            }
            bulkst_flush();
        }
        __syncthreads();
    }
}

// ===========================================================================
// Flash attention: 128-query x 64-key tiles, 2-stage, 2 CTAs/SM.
// smem: [bars 128][Qhi TB][Qlo TB][2 stages x {Kh,Kl,Vh,Vl} x KTB] = 110720
// ===========================================================================
#define AQ    128
#define AKV0  (AQ + 2 * TB)
#define ASTG  (4 * KTB)                 // 36864
#define ASMEM (AKV0 + 2 * ASTG)         // 110720

__global__ __launch_bounds__(256, 2) void attn_blk_kernel(
    const char* __restrict__ qh, const char* __restrict__ ql,
    char* __restrict__ ah, char* __restrict__ al)
{
    extern __shared__ __align__(128) char smc[];
    const uint32_t sb = smem_u32(smc);

    const int tid = threadIdx.x;
    const int lane = tid & 31;
    const int wid = tid >> 5;

    const int qt = blockIdx.x;        // 0..7
    const int bh = blockIdx.y;        // 0..191
    const int b = bh / NHEAD;
    const int h = bh % NHEAD;

    const size_t baseQ = ((size_t)((b * 3 + 0) * 12 + h)) * (16 * KTB);
    const size_t baseK = ((size_t)((b * 3 + 1) * 12 + h)) * (16 * KTB);
    const size_t baseV = ((size_t)((b * 3 + 2) * 12 + h)) * (16 * KTB);

    if (tid == 0) {
        mbar_init(sb, 1); mbar_init(sb + 8, 1); mbar_init(sb + 16, 1);
    }
    __syncthreads();

    if (tid == 0) {
        mbar_expect(sb, 2 * TB);
        bulkcp(sb + AQ,      qh + baseQ + (size_t)qt * TB, TB, sb);
        bulkcp(sb + AQ + TB, ql + baseQ + (size_t)qt * TB, TB, sb);
        mbar_expect(sb + 8, ASTG);
        bulkcp(sb + AKV0 + 0 * KTB, qh + baseK, KTB, sb + 8);
        bulkcp(sb + AKV0 + 1 * KTB, ql + baseK, KTB, sb + 8);
        bulkcp(sb + AKV0 + 2 * KTB, qh + baseV, KTB, sb + 8);
        bulkcp(sb + AKV0 + 3 * KTB, ql + baseV, KTB, sb + 8);
    }

    const uint32_t a_lm = (uint32_t)((lane & 15) * KROW + (lane >> 4) * 16);
    const uint32_t b_lm = (uint32_t)((((lane >> 4) << 3) + (lane & 7)) * KROW
                        + ((lane >> 3) & 1) * 16);

    uint32_t qfh[4][4], qfl[4][4];

    float m0 = -INFINITY, m1 = -INFINITY, l0a = 0.0f, l1a = 0.0f;
    float o[8][4];
#pragma unroll
    for (int nb = 0; nb < 8; nb++)
#pragma unroll
        for (int q = 0; q < 4; q++) o[nb][q] = 0.0f;

    uint32_t ph[2] = {0, 0};

    for (int jt = 0; jt < SEQ / 64; jt++) {     // 16 iterations
        __syncthreads();   // all done with the buffer being overwritten

        if (tid == 0 && jt + 1 < SEQ / 64) {
            const uint32_t mb = sb + 8 + ((jt + 1) & 1) * 8;
            const uint32_t bu = sb + AKV0 + ((jt + 1) & 1) * ASTG;
            const size_t go = (size_t)(jt + 1) * KTB;
            mbar_expect(mb, ASTG);
            bulkcp(bu + 0 * KTB, qh + baseK + go, KTB, mb);
            bulkcp(bu + 1 * KTB, ql + baseK + go, KTB, mb);
            bulkcp(bu + 2 * KTB, qh + baseV + go, KTB, mb);
            bulkcp(bu + 3 * KTB, ql + baseV + go, KTB, mb);
        }
        const int bs = jt & 1;
        mbar_wait(sb + 8 + bs * 8, ph[bs]);
        ph[bs] ^= 1;

        if (jt == 0) {
            mbar_wait(sb, 0);
            const uint32_t qbase = sb + AQ + (uint32_t)(wid * 16 * KROW) + a_lm;
#pragma unroll
            for (int ks = 0; ks < 4; ks++) {
                ldm_x4(qfh[ks][0], qfh[ks][1], qfh[ks][2], qfh[ks][3],
                       qbase + ks * 32);
                ldm_x4(qfl[ks][0], qfl[ks][1], qfl[ks][2], qfl[ks][3],
                       qbase + TB + ks * 32);
            }
        }

        const uint32_t st = sb + AKV0 + (uint32_t)(bs * ASTG);

        // ---- S = Q K^T over 64 keys, 3-term split ----
        float s[8][4];
#pragma unroll
        for (int nb = 0; nb < 8; nb++)
#pragma unroll
            for (int q = 0; q < 4; q++) s[nb][q] = 0.0f;

#pragma unroll
        for (int ks = 0; ks < 4; ks++) {
#pragma unroll
            for (int nb2 = 0; nb2 < 4; nb2++) {
                const uint32_t kb = st + (uint32_t)(nb2 * 16 * KROW)
                                  + b_lm + ks * 32;
                uint32_t r0, r1, r2, r3, t0, t1, t2, t3;
                ldm_x4(r0, r1, r2, r3, kb);
                ldm_x4(t0, t1, t2, t3, kb + KTB);
                uint32_t bh0[2] = {r0, r1}, bh1[2] = {r2, r3};
                uint32_t bl0[2] = {t0, t1}, bl1[2] = {t2, t3};
                mma_bf16(s[2 * nb2],     qfh[ks], bh0);
                mma_bf16(s[2 * nb2 + 1], qfh[ks], bh1);
                mma_bf16(s[2 * nb2],     qfh[ks], bl0);
                mma_bf16(s[2 * nb2 + 1], qfh[ks], bl1);
                mma_bf16(s[2 * nb2],     qfl[ks], bh0);
                mma_bf16(s[2 * nb2 + 1], qfl[ks], bh1);
            }
        }

        // ---- online softmax ----
        float mx0 = -INFINITY, mx1 = -INFINITY;
#pragma unroll
        for (int nb = 0; nb < 8; nb++) {
            s[nb][0] *= 0.125f; s[nb][1] *= 0.125f;
            s[nb][2] *= 0.125f; s[nb][3] *= 0.125f;
            mx0 = fmaxf(mx0, fmaxf(s[nb][0], s[nb][1]));
            mx1 = fmaxf(mx1, fmaxf(s[nb][2], s[nb][3]));
        }
        mx0 = fmaxf(mx0, __shfl_xor_sync(0xffffffffu, mx0, 1));
        mx0 = fmaxf(mx0, __shfl_xor_sync(0xffffffffu, mx0, 2));
        mx1 = fmaxf(mx1, __shfl_xor_sync(0xffffffffu, mx1, 1));
        mx1 = fmaxf(mx1, __shfl_xor_sync(0xffffffffu, mx1, 2));

        const float mn0 = fmaxf(m0, mx0);
        const float mn1 = fmaxf(m1, mx1);
        const float al0 = __expf(m0 - mn0);
        const float al1 = __expf(m1 - mn1);
        m0 = mn0; m1 = mn1;

        float rs0 = 0.0f, rs1 = 0.0f;
#pragma unroll
        for (int nb = 0; nb < 8; nb++) {
            s[nb][0] = __expf(s[nb][0] - m0);
            s[nb][1] = __expf(s[nb][1] - m0);
            s[nb][2] = __expf(s[nb][2] - m1);
            s[nb][3] = __expf(s[nb][3] - m1);
            rs0 += s[nb][0] + s[nb][1];
            rs1 += s[nb][2] + s[nb][3];
        }
        rs0 += __shfl_xor_sync(0xffffffffu, rs0, 1);
        rs0 += __shfl_xor_sync(0xffffffffu, rs0, 2);
        rs1 += __shfl_xor_sync(0xffffffffu, rs1, 1);
        rs1 += __shfl_xor_sync(0xffffffffu, rs1, 2);
        l0a = l0a * al0 + rs0;
        l1a = l1a * al1 + rs1;

#pragma unroll
        for (int nb = 0; nb < 8; nb++) {
            o[nb][0] *= al0; o[nb][1] *= al0;
            o[nb][2] *= al1; o[nb][3] *= al1;
        }

        // ---- O += P V (P split in regs; V via ldm.trans) ----
#pragma unroll
        for (int ks2 = 0; ks2 < 4; ks2++) {
            uint32_t pfh[4], pfl[4];
            split2(s[2 * ks2][0],     s[2 * ks2][1],     pfh[0], pfl[0]);
            split2(s[2 * ks2][2],     s[2 * ks2][3],     pfh[1], pfl[1]);
            split2(s[2 * ks2 + 1][0], s[2 * ks2 + 1][1], pfh[2], pfl[2]);
            split2(s[2 * ks2 + 1][2], s[2 * ks2 + 1][3], pfh[3], pfl[3]);
#pragma unroll
            for (int nb2 = 0; nb2 < 4; nb2++) {
                const uint32_t vb = st + 2 * KTB
                                  + (uint32_t)(ks2 * 16 * KROW)
                                  + (uint32_t)(nb2 * 32) + a_lm;
                uint32_t r0, r1, r2, r3, t0, t1, t2, t3;
                ldm_x4t(r0, r1, r2, r3, vb);
                ldm_x4t(t0, t1, t2, t3, vb + KTB);
                uint32_t vh0[2] = {r0, r1}, vh1[2] = {r2, r3};
                uint32_t vl0[2] = {t0, t1}, vl1[2] = {t2, t3};
                mma_bf16(o[2 * nb2],     pfh, vh0);
                mma_bf16(o[2 * nb2 + 1], pfh, vh1);
                mma_bf16(o[2 * nb2],     pfh, vl0);
                mma_bf16(o[2 * nb2 + 1], pfh, vl1);
                mma_bf16(o[2 * nb2],     pfl, vh0);
                mma_bf16(o[2 * nb2 + 1], pfl, vh1);
            }
        }
    }

    // ---- epilogue: normalize, split, stage into Q buffer, bulk-store ----
    const float inv0 = 1.0f / l0a;
    const float inv1 = 1.0f / l1a;
    const int row0 = wid * 16 + (lane >> 2);
#pragma unroll
    for (int nb = 0; nb < 8; nb++) {
        const int cc = (nb * 8 + (lane & 3) * 2) * 2;
        uint32_t hh, ll;
        split2(o[nb][0] * inv0, o[nb][1] * inv0, hh, ll);
        *(uint32_t*)(smc + AQ + row0 * KROW + cc) = hh;
        *(uint32_t*)(smc + AQ + TB + row0 * KROW + cc) = ll;
        split2(o[nb][2] * inv1, o[nb][3] * inv1, hh, ll);
        *(uint32_t*)(smc + AQ + (row0 + 8) * KROW + cc) = hh;
        *(uint32_t*)(smc + AQ + TB + (row0 + 8) * KROW + cc) = ll;
    }
    __syncthreads();
    if (tid == 0) {
        asm volatile("fence.proxy.async.shared::cta;" ::: "memory");
        const size_t tbase = ((size_t)(b * 8 + qt) * NKS + h) * TB;
        bulkst(ah + tbase, sb + AQ, TB);
        bulkst(al + tbase, sb + AQ + TB, TB);
        bulkst_flush();
    }
    __syncthreads();
}

// ===========================================================================
extern "C" void kernel_launch(void* const* d_in, const int* in_sizes, int n_in,
                              void* d_out, int out_size)
{
    const float* x      = (const float*)d_in[0];
    const float* w_qkv  = (const float*)d_in[1];
    const float* w_proj = (const float*)d_in[2];
    const float* b_proj = (const float*)d_in[3];
    float* out = (float*)d_out;

    char *xh, *xl, *wqh, *wql, *wph, *wpl, *qh, *ql, *ah, *al;
    cudaGetSymbolAddress((void**)&xh,  g_xhi);
    cudaGetSymbolAddress((void**)&xl,  g_xlo);
    cudaGetSymbolAddress((void**)&wqh, g_wqh);
    cudaGetSymbolAddress((void**)&wql, g_wql);
    cudaGetSymbolAddress((void**)&wph, g_wph);
    cudaGetSymbolAddress((void**)&wpl, g_wpl);
    cudaGetSymbolAddress((void**)&qh,  g_qh);
    cudaGetSymbolAddress((void**)&ql,  g_ql);
    cudaGetSymbolAddress((void**)&ah,  g_ah);
    cudaGetSymbolAddress((void**)&al,  g_al);

    cudaFuncSetAttribute(gemm_blk_kernel,
                         cudaFuncAttributeMaxDynamicSharedMemorySize, GSMEM);
    cudaFuncSetAttribute(attn_blk_kernel,
                         cudaFuncAttributeMaxDynamicSharedMemorySize, ASMEM);

    // 0) split + block inputs
    split_blk_kernel<<<M_TOK * DIM / 4 / 256, 256>>>(
        (const float4*)x, xh, xl, M_TOK * DIM / 4);
    split_blk_kernel<<<QKV_E * DIM / 4 / 256, 256>>>(
        (const float4*)w_qkv, wqh, wql, QKV_E * DIM / 4);
    split_blk_kernel<<<DIM * DIM / 4 / 256, 256>>>(
        (const float4*)w_proj, wph, wpl, DIM * DIM / 4);

    // 1) QKV projection -> blocked qkv (split)
    dim3 g1(QKV_E / 256, M_TOK / 128);   // (9, 128)
    gemm_blk_kernel<<<g1, 512, GSMEM>>>(xh, xl, wqh, wql,
                                        nullptr, nullptr, qh, ql, 0, 0);

    // 2) Attention -> blocked ao (split)
    dim3 g2(SEQ / 128, BATCH * NHEAD);   // (8, 192)
    attn_blk_kernel<<<g2, 256, ASMEM>>>(qh, ql, ah, al);

    // 3) Output projection -> fp32 out + bias
    dim3 g3(DIM / 256, M_TOK / 128);     // (3, 128)
    gemm_blk_kernel<<<g3, 512, GSMEM>>>(ah, al, wph, wpl,
                                        b_proj, out, nullptr, nullptr,
                                        DIM, 1);
}